// round 1
// baseline (speedup 1.0000x reference)
#include <cuda_runtime.h>
#include <math.h>

// Problem constants
namespace cfg {
constexpr int B = 4, S = 2048, D = 1024, H = 16, DK = 64;
constexpr long long BS = (long long)B * S;          // 8192
constexpr long long BSD = (long long)B * S * D;     // 8,388,608
}

// Scratch (device globals: allocation-free, graph-safe)
__device__ float g_q[cfg::B * cfg::S * cfg::D];
__device__ float g_k[cfg::B * cfg::S * cfg::D];
__device__ float g_v[cfg::B * cfg::S * cfg::D];
__device__ float g_attn[cfg::B * cfg::S * cfg::D];
__device__ float g_tmp[cfg::B * cfg::S * cfg::D];

#define BDIM 256

// Generic batched tiled GEMM.
//   C[z] = alpha * A[z] @ op(B[z]) (+ bias)
//   op(B) = B         if !TRANSB  (B is K x N row-major, ldb)
//   op(B) = B^T       if  TRANSB  (B is N x K row-major, ldb)
// Batch offsets: off(z) = (z/zdiv)*s1 + (z%zdiv)*s2   (per operand)
template <int BM, int BN, int BK, int TM, int TN, bool TRANSB, bool BIAS>
__global__ void gemm_k(const float* __restrict__ A, int lda, long long sA1, long long sA2,
                       const float* __restrict__ Bp, int ldb, long long sB1, long long sB2,
                       float* __restrict__ C, int ldc, long long sC1, long long sC2,
                       int M, int N, int K, int zdiv, float alpha,
                       const float* __restrict__ bias) {
    __shared__ float As[BK][BM + 1];
    __shared__ float Bs[BK][BN + 1];

    const int z = blockIdx.z;
    A  += (long long)(z / zdiv) * sA1 + (long long)(z % zdiv) * sA2;
    Bp += (long long)(z / zdiv) * sB1 + (long long)(z % zdiv) * sB2;
    C  += (long long)(z / zdiv) * sC1 + (long long)(z % zdiv) * sC2;

    const int tid = threadIdx.x;
    constexpr int TX = BN / TN;            // threads along N
    const int tx = tid % TX;
    const int ty = tid / TX;
    const int rowBase = blockIdx.y * BM;
    const int colBase = blockIdx.x * BN;

    float acc[TM][TN];
#pragma unroll
    for (int i = 0; i < TM; i++)
#pragma unroll
        for (int j = 0; j < TN; j++) acc[i][j] = 0.f;

    for (int k0 = 0; k0 < K; k0 += BK) {
        // Load A tile (BM x BK), store transposed As[k][m]
        for (int e = tid; e < BM * BK; e += BDIM) {
            int m = e / BK, k = e % BK;
            int gr = rowBase + m, gk = k0 + k;
            As[k][m] = (gr < M && gk < K) ? A[(long long)gr * lda + gk] : 0.f;
        }
        // Load B tile -> Bs[k][n]
        if (TRANSB) {
            for (int e = tid; e < BN * BK; e += BDIM) {
                int n = e / BK, k = e % BK;
                int gn = colBase + n, gk = k0 + k;
                Bs[k][n] = (gn < N && gk < K) ? Bp[(long long)gn * ldb + gk] : 0.f;
            }
        } else {
            for (int e = tid; e < BK * BN; e += BDIM) {
                int k = e / BN, n = e % BN;
                int gk = k0 + k, gn = colBase + n;
                Bs[k][n] = (gk < K && gn < N) ? Bp[(long long)gk * ldb + gn] : 0.f;
            }
        }
        __syncthreads();

#pragma unroll
        for (int kk = 0; kk < BK; kk++) {
            float ra[TM], rb[TN];
#pragma unroll
            for (int i = 0; i < TM; i++) ra[i] = As[kk][ty * TM + i];
#pragma unroll
            for (int j = 0; j < TN; j++) rb[j] = Bs[kk][tx * TN + j];
#pragma unroll
            for (int i = 0; i < TM; i++)
#pragma unroll
                for (int j = 0; j < TN; j++) acc[i][j] += ra[i] * rb[j];
        }
        __syncthreads();
    }

#pragma unroll
    for (int i = 0; i < TM; i++) {
        int gr = rowBase + ty * TM + i;
        if (gr >= M) continue;
#pragma unroll
        for (int j = 0; j < TN; j++) {
            int gn = colBase + tx * TN + j;
            if (gn >= N) continue;
            float v = alpha * acc[i][j];
            if (BIAS) v += bias[gn];
            C[(long long)gr * ldc + gn] = v;
        }
    }
}

// One-pass row softmax over 2048 columns, in place. One block (256 thr) / row.
__global__ void softmax_rows_2048(float* __restrict__ w) {
    const long long row = blockIdx.x;
    float* p = w + row * 2048LL;
    const int tid = threadIdx.x;
    constexpr int PER = 2048 / 256;  // 8

    float x[PER];
    float m = -INFINITY;
#pragma unroll
    for (int i = 0; i < PER; i++) {
        x[i] = p[tid + i * 256];
        m = fmaxf(m, x[i]);
    }
    __shared__ float sd[256];
    sd[tid] = m;
    __syncthreads();
#pragma unroll
    for (int s = 128; s > 0; s >>= 1) {
        if (tid < s) sd[tid] = fmaxf(sd[tid], sd[tid + s]);
        __syncthreads();
    }
    m = sd[0];
    __syncthreads();

    float sum = 0.f;
#pragma unroll
    for (int i = 0; i < PER; i++) {
        x[i] = __expf(x[i] - m);
        sum += x[i];
    }
    sd[tid] = sum;
    __syncthreads();
#pragma unroll
    for (int s = 128; s > 0; s >>= 1) {
        if (tid < s) sd[tid] += sd[tid + s];
        __syncthreads();
    }
    const float inv = 1.f / sd[0];
#pragma unroll
    for (int i = 0; i < PER; i++) p[tid + i * 256] = x[i] * inv;
}

extern "C" void kernel_launch(void* const* d_in, const int* in_sizes, int n_in,
                              void* d_out, int out_size) {
    using namespace cfg;
    const float* values  = (const float*)d_in[0];
    const float* keys    = (const float*)d_in[1];
    const float* queries = (const float*)d_in[2];
    const float* Wq = (const float*)d_in[3];
    const float* bq = (const float*)d_in[4];
    const float* Wk = (const float*)d_in[5];
    const float* bk = (const float*)d_in[6];
    const float* Wv = (const float*)d_in[7];
    const float* bv = (const float*)d_in[8];
    const float* Wo = (const float*)d_in[9];
    const float* bo = (const float*)d_in[10];

    float* out   = (float*)d_out;                 // [B,S,D]
    float* attnw = out + BSD;                     // [B,H,S,S]

    float *q, *k, *v, *attn, *tmp;
    cudaGetSymbolAddress((void**)&q, g_q);
    cudaGetSymbolAddress((void**)&k, g_k);
    cudaGetSymbolAddress((void**)&v, g_v);
    cudaGetSymbolAddress((void**)&attn, g_attn);
    cudaGetSymbolAddress((void**)&tmp, g_tmp);

    const long long SD = (long long)S * D;        // per-batch stride in q/k/v
    const long long SS = (long long)S * S;        // per-head stride in attnw

    // ---- QKV projections: [8192,1024] @ [1024,1024] + bias ----
    {
        dim3 grid(D / 128, (int)(BS / 128), 1);
        gemm_k<128, 128, 16, 8, 8, false, true><<<grid, BDIM>>>(
            queries, D, 0, 0, Wq, D, 0, 0, q, D, 0, 0, (int)BS, D, D, 1, 1.f, bq);
        gemm_k<128, 128, 16, 8, 8, false, true><<<grid, BDIM>>>(
            keys, D, 0, 0, Wk, D, 0, 0, k, D, 0, 0, (int)BS, D, D, 1, 1.f, bk);
        gemm_k<128, 128, 16, 8, 8, false, true><<<grid, BDIM>>>(
            values, D, 0, 0, Wv, D, 0, 0, v, D, 0, 0, (int)BS, D, D, 1, 1.f, bv);
    }

    // ---- scores = Q_h @ K_h^T / sqrt(DK), per (b,h); written into d_out ----
    {
        dim3 grid(S / 128, S / 128, B * H);
        gemm_k<128, 128, 16, 8, 8, true, false><<<grid, BDIM>>>(
            q, D, SD, DK,                 // A: offset b*S*D + h*DK
            k, D, SD, DK,                 // B (transposed use)
            attnw, S, (long long)H * SS, SS,  // C: offset (b*H+h)*S*S
            S, S, DK, H, 0.125f, nullptr);
    }

    // ---- softmax rows (B*H*S rows of 2048) ----
    softmax_rows_2048<<<B * H * S, BDIM>>>(attnw);

    // ---- attn = weights @ V_h, per (b,h) -> g_attn in [B,S,D] layout ----
    {
        dim3 grid(1, S / 128, B * H);
        gemm_k<128, 64, 16, 8, 4, false, false><<<grid, BDIM>>>(
            attnw, S, (long long)H * SS, SS,  // A: (b*H+h)*S*S
            v, D, SD, DK,                     // B: b*S*D + h*DK
            attn, D, SD, DK,                  // C: b*S*D + h*DK
            S, DK, S, H, 1.f, nullptr);
    }

    // ---- double output projection ----
    {
        dim3 grid(D / 128, (int)(BS / 128), 1);
        gemm_k<128, 128, 16, 8, 8, false, true><<<grid, BDIM>>>(
            attn, D, 0, 0, Wo, D, 0, 0, tmp, D, 0, 0, (int)BS, D, D, 1, 1.f, bo);
        gemm_k<128, 128, 16, 8, 8, false, true><<<grid, BDIM>>>(
            tmp, D, 0, 0, Wo, D, 0, 0, out, D, 0, 0, (int)BS, D, D, 1, 1.f, bo);
    }
}

// round 3
// speedup vs baseline: 3.3172x; 3.3172x over previous
#include <cuda_runtime.h>
#include <cuda_bf16.h>
#include <math.h>
#include <stdint.h>

// Problem constants
namespace cfg {
constexpr int B = 4, S = 2048, D = 1024, H = 16, DK = 64;
constexpr long long BS  = (long long)B * S;      // 8192
constexpr long long BSD = (long long)B * S * D;  // 8,388,608
}

// Scratch (device globals: allocation-free, graph-safe)
__device__ float g_q[cfg::B * cfg::S * cfg::D];
__device__ float g_k[cfg::B * cfg::S * cfg::D];
__device__ float g_v[cfg::B * cfg::S * cfg::D];
__device__ float g_vt[cfg::B * cfg::S * cfg::D];   // per-(b,h) V^T: [B][H][DK][S]
__device__ float g_attn[cfg::B * cfg::S * cfg::D];
__device__ float g_tmp[cfg::B * cfg::S * cfg::D];
__device__ float g_wqt[cfg::D * cfg::D];
__device__ float g_wkt[cfg::D * cfg::D];
__device__ float g_wvt[cfg::D * cfg::D];
__device__ float g_wot[cfg::D * cfg::D];

// ---------------------------------------------------------------------------
// Helpers (baseline-ISA only: ldmatrix + mma.sync, valid on plain sm_103)
// ---------------------------------------------------------------------------
__device__ __forceinline__ uint32_t smem_u32(const void* p) {
    uint32_t a;
    asm("{ .reg .u64 t; cvta.to.shared.u64 t, %1; cvt.u32.u64 %0, t; }"
        : "=r"(a) : "l"(p));
    return a;
}

__device__ __forceinline__ void ldsm_x4(uint32_t addr, uint32_t r[4]) {
    asm volatile("ldmatrix.sync.aligned.m8n8.x4.shared.b16 {%0,%1,%2,%3}, [%4];"
                 : "=r"(r[0]), "=r"(r[1]), "=r"(r[2]), "=r"(r[3]) : "r"(addr));
}

__device__ __forceinline__ void mma_bf16(float* c, const uint32_t* a,
                                         uint32_t b0, uint32_t b1) {
    asm volatile(
        "mma.sync.aligned.m16n8k16.row.col.f32.bf16.bf16.f32 "
        "{%0,%1,%2,%3},{%4,%5,%6,%7},{%8,%9},{%0,%1,%2,%3};"
        : "+f"(c[0]), "+f"(c[1]), "+f"(c[2]), "+f"(c[3])
        : "r"(a[0]), "r"(a[1]), "r"(a[2]), "r"(a[3]), "r"(b0), "r"(b1));
}

// 128B-block XOR swizzle (bits[6:4] ^= bits[9:7]) — conflict-free ldmatrix
#define SWZ(o) ((o) ^ (((o) >> 3) & 0x70))

// Split fp32 pair into packed bf16x2 (hi) and packed bf16x2 residual (lo)
__device__ __forceinline__ void split2(float a, float b, uint32_t& hi, uint32_t& lo) {
    __nv_bfloat16 ha = __float2bfloat16_rn(a);
    __nv_bfloat16 hb = __float2bfloat16_rn(b);
    __nv_bfloat16 la = __float2bfloat16_rn(a - __bfloat162float(ha));
    __nv_bfloat16 lb = __float2bfloat16_rn(b - __bfloat162float(hb));
    hi = (uint32_t)__bfloat16_as_ushort(ha) | ((uint32_t)__bfloat16_as_ushort(hb) << 16);
    lo = (uint32_t)__bfloat16_as_ushort(la) | ((uint32_t)__bfloat16_as_ushort(lb) << 16);
}

// ---------------------------------------------------------------------------
// Tensor-core GEMM via mma.sync:  C[M,N] = alpha * A[M,K] @ Bt[N,K]^T (+ bias)
// A row-major (lda), Bt row-major (ldb) — both K-major.
// 2-term bf16 split: C = Ahi*Bhi + Ahi*Blo + Alo*Bhi  (error ~2^-18).
// CTA tile: 128 x N_TILE, K chunk 64. 8 warps (2 M x 4 N).
// Batch offsets: ptr += (z/zdiv)*s1 + (z%zdiv)*s2
// ---------------------------------------------------------------------------
template <int N_TILE, bool BIAS>
__global__ __launch_bounds__(256, 1) void gemm_mma(
    const float* __restrict__ A, int lda, long long sA1, long long sA2,
    const float* __restrict__ Bt, int ldb, long long sB1, long long sB2,
    float* __restrict__ C, int ldc, long long sC1, long long sC2,
    int K, int zdiv, float alpha, const float* __restrict__ bias) {
    extern __shared__ __align__(1024) char smem[];
    constexpr int OFF_AHI = 0;
    constexpr int OFF_ALO = 128 * 128;           // 16 KB (128 rows x 128B)
    constexpr int OFF_BHI = 2 * 128 * 128;       // 32 KB
    constexpr int OFF_BLO = OFF_BHI + N_TILE * 128;

    constexpr int WN = N_TILE / 4;    // warp N extent (32 or 16)
    constexpr int NLD = WN / 16;      // x4 B loads per warp per k-step (2 or 1)
    constexpr int NFRAG = WN / 8;     // n8 frags per warp (4 or 2)

    const uint32_t sb = smem_u32(smem);
    const int tid = threadIdx.x;
    const int lane = tid & 31;
    const int w = tid >> 5;
    const int wm = w & 1;             // 2 warps along M (64 rows each)
    const int wn = w >> 1;            // 4 warps along N (WN cols each)

    const int z = blockIdx.z;
    A  += (long long)(z / zdiv) * sA1 + (long long)(z % zdiv) * sA2;
    Bt += (long long)(z / zdiv) * sB1 + (long long)(z % zdiv) * sB2;
    C  += (long long)(z / zdiv) * sC1 + (long long)(z % zdiv) * sC2;

    const int rowBase = blockIdx.y * 128;
    const int colBase = blockIdx.x * N_TILE;

    float acc[4][NFRAG][4];
#pragma unroll
    for (int i = 0; i < 4; i++)
#pragma unroll
        for (int j = 0; j < NFRAG; j++)
#pragma unroll
            for (int e = 0; e < 4; e++) acc[i][j][e] = 0.f;

    // ldmatrix lane address components (same formula for A and B frags):
    // row-in-tile = fragRowBase + (lane % 16), k-chunk(16B) = kk*2 + lane/16
    const int lrow = lane & 15;
    const int lkh = lane >> 4;

    for (int k0 = 0; k0 < K; k0 += 64) {
        // ---- load + split A tile: 128 rows x 64 fp32 ----
#pragma unroll
        for (int i = 0; i < 8; i++) {
            int e = tid + i * 256;
            int r = e >> 4, q = e & 15;
            float4 x = *(const float4*)(A + (long long)(rowBase + r) * lda + k0 + q * 4);
            uint32_t h01, l01, h23, l23;
            split2(x.x, x.y, h01, l01);
            split2(x.z, x.w, h23, l23);
            uint32_t off = SWZ((uint32_t)(r * 128 + q * 8));
            *(uint2*)(smem + OFF_AHI + off) = make_uint2(h01, h23);
            *(uint2*)(smem + OFF_ALO + off) = make_uint2(l01, l23);
        }
        // ---- load + split B tile: N_TILE rows x 64 fp32 ----
#pragma unroll
        for (int i = 0; i < N_TILE / 16; i++) {
            int e = tid + i * 256;
            int r = e >> 4, q = e & 15;
            float4 x = *(const float4*)(Bt + (long long)(colBase + r) * ldb + k0 + q * 4);
            uint32_t h01, l01, h23, l23;
            split2(x.x, x.y, h01, l01);
            split2(x.z, x.w, h23, l23);
            uint32_t off = SWZ((uint32_t)(r * 128 + q * 8));
            *(uint2*)(smem + OFF_BHI + off) = make_uint2(h01, h23);
            *(uint2*)(smem + OFF_BLO + off) = make_uint2(l01, l23);
        }
        __syncthreads();

        // ---- 4 k-steps of 16 ----
#pragma unroll
        for (int kk = 0; kk < 4; kk++) {
            const int kc = kk * 2 + lkh;
            uint32_t ahi[4][4], alo[4][4];
#pragma unroll
            for (int fm = 0; fm < 4; fm++) {
                uint32_t off = SWZ((uint32_t)((wm * 64 + fm * 16 + lrow) * 128 + kc * 16));
                ldsm_x4(sb + OFF_AHI + off, ahi[fm]);
                ldsm_x4(sb + OFF_ALO + off, alo[fm]);
            }
            uint32_t bhi[NLD][4], blo[NLD][4];
#pragma unroll
            for (int fp = 0; fp < NLD; fp++) {
                uint32_t off = SWZ((uint32_t)((wn * WN + fp * 16 + lrow) * 128 + kc * 16));
                ldsm_x4(sb + OFF_BHI + off, bhi[fp]);
                ldsm_x4(sb + OFF_BLO + off, blo[fp]);
            }
#pragma unroll
            for (int fm = 0; fm < 4; fm++) {
#pragma unroll
                for (int fn = 0; fn < NFRAG; fn++) {
                    const int fp = fn >> 1, sel = fn & 1;
                    uint32_t bh0 = bhi[fp][sel], bh1 = bhi[fp][sel + 2];
                    uint32_t bl0 = blo[fp][sel], bl1 = blo[fp][sel + 2];
                    mma_bf16(acc[fm][fn], ahi[fm], bh0, bh1);
                    mma_bf16(acc[fm][fn], ahi[fm], bl0, bl1);
                    mma_bf16(acc[fm][fn], alo[fm], bh0, bh1);
                }
            }
        }
        __syncthreads();
    }

    // ---- epilogue: registers -> gmem (float2 stores) ----
    const int erow = rowBase + wm * 64 + (lane >> 2);
    const int ecol = colBase + wn * WN + (lane & 3) * 2;
#pragma unroll
    for (int fm = 0; fm < 4; fm++) {
#pragma unroll
        for (int fn = 0; fn < NFRAG; fn++) {
            int cc = ecol + fn * 8;
            float b0 = BIAS ? bias[cc] : 0.f;
            float b1 = BIAS ? bias[cc + 1] : 0.f;
            int r0 = erow + fm * 16;
            float2 v0 = make_float2(acc[fm][fn][0] * alpha + b0,
                                    acc[fm][fn][1] * alpha + b1);
            float2 v1 = make_float2(acc[fm][fn][2] * alpha + b0,
                                    acc[fm][fn][3] * alpha + b1);
            *(float2*)(C + (long long)r0 * ldc + cc) = v0;
            *(float2*)(C + (long long)(r0 + 8) * ldc + cc) = v1;
        }
    }
}

// ---------------------------------------------------------------------------
// Tiled transpose: out[z][c][r] = in[.][r][c]
// in += (z/zdiv)*si1 + (z%zdiv)*si2 ; out += z*so
// ---------------------------------------------------------------------------
__global__ void transpose_g(const float* __restrict__ in, int ldi,
                            long long si1, long long si2,
                            float* __restrict__ out, int ldo, long long so,
                            int zdiv) {
    __shared__ float tile[32][33];
    const int z = blockIdx.z;
    in  += (long long)(z / zdiv) * si1 + (long long)(z % zdiv) * si2;
    out += (long long)z * so;
    const int bx = blockIdx.x * 32;
    const int by = blockIdx.y * 32;
    const int tx = threadIdx.x, ty = threadIdx.y;  // 32 x 8
#pragma unroll
    for (int i = 0; i < 32; i += 8)
        tile[ty + i][tx] = in[(long long)(by + ty + i) * ldi + bx + tx];
    __syncthreads();
#pragma unroll
    for (int i = 0; i < 32; i += 8)
        out[(long long)(bx + ty + i) * ldo + by + tx] = tile[tx][ty + i];
}

// One-pass row softmax over 2048 columns, in place. One block (256 thr) / row.
__global__ void softmax_rows_2048(float* __restrict__ w) {
    const long long row = blockIdx.x;
    float* p = w + row * 2048LL;
    const int tid = threadIdx.x;
    constexpr int PER = 8;

    float x[PER];
    float m = -INFINITY;
#pragma unroll
    for (int i = 0; i < PER; i++) {
        x[i] = p[tid + i * 256];
        m = fmaxf(m, x[i]);
    }
    __shared__ float sd[256];
    sd[tid] = m;
    __syncthreads();
#pragma unroll
    for (int s = 128; s > 0; s >>= 1) {
        if (tid < s) sd[tid] = fmaxf(sd[tid], sd[tid + s]);
        __syncthreads();
    }
    m = sd[0];
    __syncthreads();

    float sum = 0.f;
#pragma unroll
    for (int i = 0; i < PER; i++) {
        x[i] = __expf(x[i] - m);
        sum += x[i];
    }
    sd[tid] = sum;
    __syncthreads();
#pragma unroll
    for (int s = 128; s > 0; s >>= 1) {
        if (tid < s) sd[tid] += sd[tid + s];
        __syncthreads();
    }
    const float inv = 1.f / sd[0];
#pragma unroll
    for (int i = 0; i < PER; i++) p[tid + i * 256] = x[i] * inv;
}

extern "C" void kernel_launch(void* const* d_in, const int* in_sizes, int n_in,
                              void* d_out, int out_size) {
    using namespace cfg;
    const float* values  = (const float*)d_in[0];
    const float* keys    = (const float*)d_in[1];
    const float* queries = (const float*)d_in[2];
    const float* Wq = (const float*)d_in[3];
    const float* bq = (const float*)d_in[4];
    const float* Wk = (const float*)d_in[5];
    const float* bk = (const float*)d_in[6];
    const float* Wv = (const float*)d_in[7];
    const float* bv = (const float*)d_in[8];
    const float* Wo = (const float*)d_in[9];
    const float* bo = (const float*)d_in[10];

    float* out   = (float*)d_out;  // [B,S,D]
    float* attnw = out + BSD;      // [B,H,S,S]

    float *q, *k, *v, *vt, *attn, *tmp, *wqt, *wkt, *wvt, *wot;
    cudaGetSymbolAddress((void**)&q, g_q);
    cudaGetSymbolAddress((void**)&k, g_k);
    cudaGetSymbolAddress((void**)&v, g_v);
    cudaGetSymbolAddress((void**)&vt, g_vt);
    cudaGetSymbolAddress((void**)&attn, g_attn);
    cudaGetSymbolAddress((void**)&tmp, g_tmp);
    cudaGetSymbolAddress((void**)&wqt, g_wqt);
    cudaGetSymbolAddress((void**)&wkt, g_wkt);
    cudaGetSymbolAddress((void**)&wvt, g_wvt);
    cudaGetSymbolAddress((void**)&wot, g_wot);

    constexpr int SMEM_N128 = 2 * 128 * 128 + 2 * 128 * 128;  // 65536
    constexpr int SMEM_N64  = 2 * 128 * 128 + 2 * 64 * 128;   // 49152
    cudaFuncSetAttribute(gemm_mma<128, true>,
                         cudaFuncAttributeMaxDynamicSharedMemorySize, SMEM_N128);
    cudaFuncSetAttribute(gemm_mma<128, false>,
                         cudaFuncAttributeMaxDynamicSharedMemorySize, SMEM_N128);
    cudaFuncSetAttribute(gemm_mma<64, false>,
                         cudaFuncAttributeMaxDynamicSharedMemorySize, SMEM_N64);

    const long long SD = (long long)S * D;  // per-batch stride
    const long long SS = (long long)S * S;  // per-head stride in attnw

    // ---- transpose weights (D x D each) ----
    {
        dim3 blk(32, 8), grid(D / 32, D / 32, 1);
        transpose_g<<<grid, blk>>>(Wq, D, 0, 0, wqt, D, 0, 1);
        transpose_g<<<grid, blk>>>(Wk, D, 0, 0, wkt, D, 0, 1);
        transpose_g<<<grid, blk>>>(Wv, D, 0, 0, wvt, D, 0, 1);
        transpose_g<<<grid, blk>>>(Wo, D, 0, 0, wot, D, 0, 1);
    }

    // ---- QKV projections: [8192,1024] @ Wt^T + bias ----
    {
        dim3 grid(D / 128, (int)(BS / 128), 1);
        gemm_mma<128, true><<<grid, 256, SMEM_N128>>>(
            queries, D, 0, 0, wqt, D, 0, 0, q, D, 0, 0, D, 1, 1.f, bq);
        gemm_mma<128, true><<<grid, 256, SMEM_N128>>>(
            keys, D, 0, 0, wkt, D, 0, 0, k, D, 0, 0, D, 1, 1.f, bk);
        gemm_mma<128, true><<<grid, 256, SMEM_N128>>>(
            values, D, 0, 0, wvt, D, 0, 0, v, D, 0, 0, D, 1, 1.f, bv);
    }

    // ---- transpose V per (b,h): [S, DK] -> [DK, S] ----
    {
        dim3 blk(32, 8), grid(DK / 32, S / 32, B * H);
        transpose_g<<<grid, blk>>>(v, D, SD, (long long)DK, vt, S,
                                   (long long)DK * S, H);
    }

    // ---- scores = Q_h @ K_h^T / 8 -> attnw ----
    {
        dim3 grid(S / 128, S / 128, B * H);
        gemm_mma<128, false><<<grid, 256, SMEM_N128>>>(
            q, D, SD, (long long)DK,
            k, D, SD, (long long)DK,
            attnw, S, (long long)H * SS, SS,
            DK, H, 0.125f, nullptr);
    }

    // ---- softmax rows (B*H*S rows of 2048) ----
    softmax_rows_2048<<<B * H * S, 256>>>(attnw);

    // ---- attn = weights @ V_h  (Bt = V^T slice [DK, S]) ----
    {
        dim3 grid(1, S / 128, B * H);
        gemm_mma<64, false><<<grid, 256, SMEM_N64>>>(
            attnw, S, (long long)H * SS, SS,
            vt, S, (long long)H * DK * S, (long long)DK * S,
            attn, D, SD, (long long)DK,
            S, H, 1.f, nullptr);
    }

    // ---- double output projection ----
    {
        dim3 grid(D / 128, (int)(BS / 128), 1);
        gemm_mma<128, true><<<grid, 256, SMEM_N128>>>(
            attn, D, 0, 0, wot, D, 0, 0, tmp, D, 0, 0, D, 1, 1.f, bo);
        gemm_mma<128, true><<<grid, 256, SMEM_N128>>>(
            tmp, D, 0, 0, wot, D, 0, 0, out, D, 0, 0, D, 1, 1.f, bo);
    }
}

// round 4
// speedup vs baseline: 3.3277x; 1.0032x over previous
#include <cuda_runtime.h>
#include <cuda_bf16.h>
#include <math.h>
#include <stdint.h>

// Problem constants
namespace cfg {
constexpr int B = 4, S = 2048, D = 1024, H = 16, DK = 64;
constexpr long long BS  = (long long)B * S;      // 8192
constexpr long long BSD = (long long)B * S * D;  // 8,388,608
}

// Scratch (device globals: allocation-free, graph-safe)
__device__ float g_q[cfg::B * cfg::S * cfg::D];
__device__ float g_k[cfg::B * cfg::S * cfg::D];
__device__ float g_v[cfg::B * cfg::S * cfg::D];
__device__ float g_vt[cfg::B * cfg::S * cfg::D];   // per-(b,h) V^T: [B][H][DK][S]
__device__ float g_attn[cfg::B * cfg::S * cfg::D];
__device__ float g_tmp[cfg::B * cfg::S * cfg::D];
__device__ float g_wqt[cfg::D * cfg::D];
__device__ float g_wkt[cfg::D * cfg::D];
__device__ float g_wvt[cfg::D * cfg::D];
__device__ float g_wot[cfg::D * cfg::D];

// ---------------------------------------------------------------------------
// Helpers (baseline-ISA only: ldmatrix + mma.sync, valid on plain sm_103)
// ---------------------------------------------------------------------------
__device__ __forceinline__ uint32_t smem_u32(const void* p) {
    uint32_t a;
    asm("{ .reg .u64 t; cvta.to.shared.u64 t, %1; cvt.u32.u64 %0, t; }"
        : "=r"(a) : "l"(p));
    return a;
}

__device__ __forceinline__ void ldsm_x4(uint32_t addr, uint32_t r[4]) {
    asm volatile("ldmatrix.sync.aligned.m8n8.x4.shared.b16 {%0,%1,%2,%3}, [%4];"
                 : "=r"(r[0]), "=r"(r[1]), "=r"(r[2]), "=r"(r[3]) : "r"(addr));
}

__device__ __forceinline__ void mma_bf16(float* c, const uint32_t* a,
                                         uint32_t b0, uint32_t b1) {
    asm volatile(
        "mma.sync.aligned.m16n8k16.row.col.f32.bf16.bf16.f32 "
        "{%0,%1,%2,%3},{%4,%5,%6,%7},{%8,%9},{%0,%1,%2,%3};"
        : "+f"(c[0]), "+f"(c[1]), "+f"(c[2]), "+f"(c[3])
        : "r"(a[0]), "r"(a[1]), "r"(a[2]), "r"(a[3]), "r"(b0), "r"(b1));
}

// 128B-block XOR swizzle (bits[6:4] ^= bits[9:7]) — conflict-free ldmatrix
#define SWZ(o) ((o) ^ (((o) >> 3) & 0x70))

// Split fp32 pair into packed bf16x2 (hi) and packed bf16x2 residual (lo)
__device__ __forceinline__ void split2(float a, float b, uint32_t& hi, uint32_t& lo) {
    __nv_bfloat16 ha = __float2bfloat16_rn(a);
    __nv_bfloat16 hb = __float2bfloat16_rn(b);
    __nv_bfloat16 la = __float2bfloat16_rn(a - __bfloat162float(ha));
    __nv_bfloat16 lb = __float2bfloat16_rn(b - __bfloat162float(hb));
    hi = (uint32_t)__bfloat16_as_ushort(ha) | ((uint32_t)__bfloat16_as_ushort(hb) << 16);
    lo = (uint32_t)__bfloat16_as_ushort(la) | ((uint32_t)__bfloat16_as_ushort(lb) << 16);
}

// ---------------------------------------------------------------------------
// Tensor-core GEMM via mma.sync:  C[M,N] = alpha * A[M,K] @ Bt[N,K]^T (+ bias)
// A row-major (lda), Bt row-major (ldb) — both K-major.
// 2-term bf16 split: C = Ahi*Bhi + Ahi*Blo + Alo*Bhi  (error ~2^-18).
// CTA tile: 128 x N_TILE, K chunk 64. 8 warps (2 M x 4 N).
// Batch offsets: ptr += (z/zdiv)*s1 + (z%zdiv)*s2
// ---------------------------------------------------------------------------
template <int N_TILE, bool BIAS>
__global__ __launch_bounds__(256, 1) void gemm_mma(
    const float* __restrict__ A, int lda, long long sA1, long long sA2,
    const float* __restrict__ Bt, int ldb, long long sB1, long long sB2,
    float* __restrict__ C, int ldc, long long sC1, long long sC2,
    int K, int zdiv, float alpha, const float* __restrict__ bias) {
    extern __shared__ __align__(1024) char smem[];
    constexpr int OFF_AHI = 0;
    constexpr int OFF_ALO = 128 * 128;           // 16 KB (128 rows x 128B)
    constexpr int OFF_BHI = 2 * 128 * 128;       // 32 KB
    constexpr int OFF_BLO = OFF_BHI + N_TILE * 128;

    constexpr int WN = N_TILE / 4;    // warp N extent (32 or 16)
    constexpr int NLD = WN / 16;      // x4 B loads per warp per k-step (2 or 1)
    constexpr int NFRAG = WN / 8;     // n8 frags per warp (4 or 2)

    const uint32_t sb = smem_u32(smem);
    const int tid = threadIdx.x;
    const int lane = tid & 31;
    const int w = tid >> 5;
    const int wm = w & 1;             // 2 warps along M (64 rows each)
    const int wn = w >> 1;            // 4 warps along N (WN cols each)

    const int z = blockIdx.z;
    A  += (long long)(z / zdiv) * sA1 + (long long)(z % zdiv) * sA2;
    Bt += (long long)(z / zdiv) * sB1 + (long long)(z % zdiv) * sB2;
    C  += (long long)(z / zdiv) * sC1 + (long long)(z % zdiv) * sC2;

    const int rowBase = blockIdx.y * 128;
    const int colBase = blockIdx.x * N_TILE;

    float acc[4][NFRAG][4];
#pragma unroll
    for (int i = 0; i < 4; i++)
#pragma unroll
        for (int j = 0; j < NFRAG; j++)
#pragma unroll
            for (int e = 0; e < 4; e++) acc[i][j][e] = 0.f;

    // ldmatrix lane address components (same formula for A and B frags):
    // row-in-tile = fragRowBase + (lane % 16), k-chunk(16B) = kk*2 + lane/16
    const int lrow = lane & 15;
    const int lkh = lane >> 4;

    for (int k0 = 0; k0 < K; k0 += 64) {
        // ---- load + split A tile: 128 rows x 64 fp32 ----
#pragma unroll
        for (int i = 0; i < 8; i++) {
            int e = tid + i * 256;
            int r = e >> 4, q = e & 15;
            float4 x = *(const float4*)(A + (long long)(rowBase + r) * lda + k0 + q * 4);
            uint32_t h01, l01, h23, l23;
            split2(x.x, x.y, h01, l01);
            split2(x.z, x.w, h23, l23);
            uint32_t off = SWZ((uint32_t)(r * 128 + q * 8));
            *(uint2*)(smem + OFF_AHI + off) = make_uint2(h01, h23);
            *(uint2*)(smem + OFF_ALO + off) = make_uint2(l01, l23);
        }
        // ---- load + split B tile: N_TILE rows x 64 fp32 ----
#pragma unroll
        for (int i = 0; i < N_TILE / 16; i++) {
            int e = tid + i * 256;
            int r = e >> 4, q = e & 15;
            float4 x = *(const float4*)(Bt + (long long)(colBase + r) * ldb + k0 + q * 4);
            uint32_t h01, l01, h23, l23;
            split2(x.x, x.y, h01, l01);
            split2(x.z, x.w, h23, l23);
            uint32_t off = SWZ((uint32_t)(r * 128 + q * 8));
            *(uint2*)(smem + OFF_BHI + off) = make_uint2(h01, h23);
            *(uint2*)(smem + OFF_BLO + off) = make_uint2(l01, l23);
        }
        __syncthreads();

        // ---- 4 k-steps of 16 ----
#pragma unroll
        for (int kk = 0; kk < 4; kk++) {
            const int kc = kk * 2 + lkh;
            uint32_t ahi[4][4], alo[4][4];
#pragma unroll
            for (int fm = 0; fm < 4; fm++) {
                uint32_t off = SWZ((uint32_t)((wm * 64 + fm * 16 + lrow) * 128 + kc * 16));
                ldsm_x4(sb + OFF_AHI + off, ahi[fm]);
                ldsm_x4(sb + OFF_ALO + off, alo[fm]);
            }
            uint32_t bhi[NLD][4], blo[NLD][4];
#pragma unroll
            for (int fp = 0; fp < NLD; fp++) {
                uint32_t off = SWZ((uint32_t)((wn * WN + fp * 16 + lrow) * 128 + kc * 16));
                ldsm_x4(sb + OFF_BHI + off, bhi[fp]);
                ldsm_x4(sb + OFF_BLO + off, blo[fp]);
            }
#pragma unroll
            for (int fm = 0; fm < 4; fm++) {
#pragma unroll
                for (int fn = 0; fn < NFRAG; fn++) {
                    const int fp = fn >> 1, sel = fn & 1;
                    uint32_t bh0 = bhi[fp][sel], bh1 = bhi[fp][sel + 2];
                    uint32_t bl0 = blo[fp][sel], bl1 = blo[fp][sel + 2];
                    mma_bf16(acc[fm][fn], ahi[fm], bh0, bh1);
                    mma_bf16(acc[fm][fn], ahi[fm], bl0, bl1);
                    mma_bf16(acc[fm][fn], alo[fm], bh0, bh1);
                }
            }
        }
        __syncthreads();
    }

    // ---- epilogue: registers -> gmem (float2 stores) ----
    const int erow = rowBase + wm * 64 + (lane >> 2);
    const int ecol = colBase + wn * WN + (lane & 3) * 2;
#pragma unroll
    for (int fm = 0; fm < 4; fm++) {
#pragma unroll
        for (int fn = 0; fn < NFRAG; fn++) {
            int cc = ecol + fn * 8;
            float b0 = BIAS ? bias[cc] : 0.f;
            float b1 = BIAS ? bias[cc + 1] : 0.f;
            int r0 = erow + fm * 16;
            float2 v0 = make_float2(acc[fm][fn][0] * alpha + b0,
                                    acc[fm][fn][1] * alpha + b1);
            float2 v1 = make_float2(acc[fm][fn][2] * alpha + b0,
                                    acc[fm][fn][3] * alpha + b1);
            *(float2*)(C + (long long)r0 * ldc + cc) = v0;
            *(float2*)(C + (long long)(r0 + 8) * ldc + cc) = v1;
        }
    }
}

// ---------------------------------------------------------------------------
// Tiled transpose: out[z][c][r] = in[.][r][c]
// in += (z/zdiv)*si1 + (z%zdiv)*si2 ; out += z*so
// ---------------------------------------------------------------------------
__global__ void transpose_g(const float* __restrict__ in, int ldi,
                            long long si1, long long si2,
                            float* __restrict__ out, int ldo, long long so,
                            int zdiv) {
    __shared__ float tile[32][33];
    const int z = blockIdx.z;
    in  += (long long)(z / zdiv) * si1 + (long long)(z % zdiv) * si2;
    out += (long long)z * so;
    const int bx = blockIdx.x * 32;
    const int by = blockIdx.y * 32;
    const int tx = threadIdx.x, ty = threadIdx.y;  // 32 x 8
#pragma unroll
    for (int i = 0; i < 32; i += 8)
        tile[ty + i][tx] = in[(long long)(by + ty + i) * ldi + bx + tx];
    __syncthreads();
#pragma unroll
    for (int i = 0; i < 32; i += 8)
        out[(long long)(bx + ty + i) * ldo + by + tx] = tile[tx][ty + i];
}

// One-pass row softmax over 2048 columns, in place. One block (256 thr) / row.
__global__ void softmax_rows_2048(float* __restrict__ w) {
    const long long row = blockIdx.x;
    float* p = w + row * 2048LL;
    const int tid = threadIdx.x;
    constexpr int PER = 8;

    float x[PER];
    float m = -INFINITY;
#pragma unroll
    for (int i = 0; i < PER; i++) {
        x[i] = p[tid + i * 256];
        m = fmaxf(m, x[i]);
    }
    __shared__ float sd[256];
    sd[tid] = m;
    __syncthreads();
#pragma unroll
    for (int s = 128; s > 0; s >>= 1) {
        if (tid < s) sd[tid] = fmaxf(sd[tid], sd[tid + s]);
        __syncthreads();
    }
    m = sd[0];
    __syncthreads();

    float sum = 0.f;
#pragma unroll
    for (int i = 0; i < PER; i++) {
        x[i] = __expf(x[i] - m);
        sum += x[i];
    }
    sd[tid] = sum;
    __syncthreads();
#pragma unroll
    for (int s = 128; s > 0; s >>= 1) {
        if (tid < s) sd[tid] += sd[tid + s];
        __syncthreads();
    }
    const float inv = 1.f / sd[0];
#pragma unroll
    for (int i = 0; i < PER; i++) p[tid + i * 256] = x[i] * inv;
}

extern "C" void kernel_launch(void* const* d_in, const int* in_sizes, int n_in,
                              void* d_out, int out_size) {
    using namespace cfg;
    const float* values  = (const float*)d_in[0];
    const float* keys    = (const float*)d_in[1];
    const float* queries = (const float*)d_in[2];
    const float* Wq = (const float*)d_in[3];
    const float* bq = (const float*)d_in[4];
    const float* Wk = (const float*)d_in[5];
    const float* bk = (const float*)d_in[6];
    const float* Wv = (const float*)d_in[7];
    const float* bv = (const float*)d_in[8];
    const float* Wo = (const float*)d_in[9];
    const float* bo = (const float*)d_in[10];

    float* out   = (float*)d_out;  // [B,S,D]
    float* attnw = out + BSD;      // [B,H,S,S]

    float *q, *k, *v, *vt, *attn, *tmp, *wqt, *wkt, *wvt, *wot;
    cudaGetSymbolAddress((void**)&q, g_q);
    cudaGetSymbolAddress((void**)&k, g_k);
    cudaGetSymbolAddress((void**)&v, g_v);
    cudaGetSymbolAddress((void**)&vt, g_vt);
    cudaGetSymbolAddress((void**)&attn, g_attn);
    cudaGetSymbolAddress((void**)&tmp, g_tmp);
    cudaGetSymbolAddress((void**)&wqt, g_wqt);
    cudaGetSymbolAddress((void**)&wkt, g_wkt);
    cudaGetSymbolAddress((void**)&wvt, g_wvt);
    cudaGetSymbolAddress((void**)&wot, g_wot);

    constexpr int SMEM_N128 = 2 * 128 * 128 + 2 * 128 * 128;  // 65536
    constexpr int SMEM_N64  = 2 * 128 * 128 + 2 * 64 * 128;   // 49152
    cudaFuncSetAttribute(gemm_mma<128, true>,
                         cudaFuncAttributeMaxDynamicSharedMemorySize, SMEM_N128);
    cudaFuncSetAttribute(gemm_mma<128, false>,
                         cudaFuncAttributeMaxDynamicSharedMemorySize, SMEM_N128);
    cudaFuncSetAttribute(gemm_mma<64, false>,
                         cudaFuncAttributeMaxDynamicSharedMemorySize, SMEM_N64);

    const long long SD = (long long)S * D;  // per-batch stride
    const long long SS = (long long)S * S;  // per-head stride in attnw

    // ---- transpose weights (D x D each) ----
    {
        dim3 blk(32, 8), grid(D / 32, D / 32, 1);
        transpose_g<<<grid, blk>>>(Wq, D, 0, 0, wqt, D, 0, 1);
        transpose_g<<<grid, blk>>>(Wk, D, 0, 0, wkt, D, 0, 1);
        transpose_g<<<grid, blk>>>(Wv, D, 0, 0, wvt, D, 0, 1);
        transpose_g<<<grid, blk>>>(Wo, D, 0, 0, wot, D, 0, 1);
    }

    // ---- QKV projections: [8192,1024] @ Wt^T + bias ----
    {
        dim3 grid(D / 128, (int)(BS / 128), 1);
        gemm_mma<128, true><<<grid, 256, SMEM_N128>>>(
            queries, D, 0, 0, wqt, D, 0, 0, q, D, 0, 0, D, 1, 1.f, bq);
        gemm_mma<128, true><<<grid, 256, SMEM_N128>>>(
            keys, D, 0, 0, wkt, D, 0, 0, k, D, 0, 0, D, 1, 1.f, bk);
        gemm_mma<128, true><<<grid, 256, SMEM_N128>>>(
            values, D, 0, 0, wvt, D, 0, 0, v, D, 0, 0, D, 1, 1.f, bv);
    }

    // ---- transpose V per (b,h): [S, DK] -> [DK, S] ----
    {
        dim3 blk(32, 8), grid(DK / 32, S / 32, B * H);
        transpose_g<<<grid, blk>>>(v, D, SD, (long long)DK, vt, S,
                                   (long long)DK * S, H);
    }

    // ---- scores = Q_h @ K_h^T / 8 -> attnw ----
    {
        dim3 grid(S / 128, S / 128, B * H);
        gemm_mma<128, false><<<grid, 256, SMEM_N128>>>(
            q, D, SD, (long long)DK,
            k, D, SD, (long long)DK,
            attnw, S, (long long)H * SS, SS,
            DK, H, 0.125f, nullptr);
    }

    // ---- softmax rows (B*H*S rows of 2048) ----
    softmax_rows_2048<<<B * H * S, 256>>>(attnw);

    // ---- attn = weights @ V_h  (Bt = V^T slice [DK, S]) ----
    {
        dim3 grid(1, S / 128, B * H);
        gemm_mma<64, false><<<grid, 256, SMEM_N64>>>(
            attnw, S, (long long)H * SS, SS,
            vt, S, (long long)H * DK * S, (long long)DK * S,
            attn, D, SD, (long long)DK,
            S, H, 1.f, nullptr);
    }

    // ---- double output projection ----
    {
        dim3 grid(D / 128, (int)(BS / 128), 1);
        gemm_mma<128, true><<<grid, 256, SMEM_N128>>>(
            attn, D, 0, 0, wot, D, 0, 0, tmp, D, 0, 0, D, 1, 1.f, bo);
        gemm_mma<128, true><<<grid, 256, SMEM_N128>>>(
            tmp, D, 0, 0, wot, D, 0, 0, out, D, 0, 0, D, 1, 1.f, bo);
    }
}

// round 5
// speedup vs baseline: 4.3232x; 1.2992x over previous
#include <cuda_runtime.h>
#include <cuda_bf16.h>
#include <math.h>
#include <stdint.h>

namespace cfg {
constexpr int B = 4, S = 2048, D = 1024, H = 16, DK = 64;
constexpr long long BS  = (long long)B * S;
constexpr long long BSD = (long long)B * S * D;
constexpr long long SS  = (long long)S * S;
}

// Device-global scratch (allocation-free, graph-safe)
__device__ float g_q[cfg::B * cfg::S * cfg::D];
__device__ float g_k[cfg::B * cfg::S * cfg::D];
__device__ float g_v[cfg::B * cfg::S * cfg::D];
__device__ float g_vt[cfg::B * cfg::S * cfg::D];   // per-(b,h) V^T: [64][DK][S]
__device__ float g_attn[cfg::B * cfg::S * cfg::D];
__device__ float g_wqt[cfg::D * cfg::D];
__device__ float g_wkt[cfg::D * cfg::D];
__device__ float g_wvt[cfg::D * cfg::D];
__device__ float g_wot[cfg::D * cfg::D];
__device__ float g_wot2[cfg::D * cfg::D];          // (Wo@Wo)^T
__device__ float g_bo2[cfg::D];                    // bo@Wo + bo
__device__ float g_partials[64LL * 16 * 2048];     // per-tile row sums
__device__ float g_inv[64 * 2048];                 // 1/rowsum

// ---------------------------------------------------------------------------
__device__ __forceinline__ uint32_t smem_u32(const void* p) {
    uint32_t a;
    asm("{ .reg .u64 t; cvta.to.shared.u64 t, %1; cvt.u32.u64 %0, t; }"
        : "=r"(a) : "l"(p));
    return a;
}
__device__ __forceinline__ void ldsm_x4(uint32_t addr, uint32_t r[4]) {
    asm volatile("ldmatrix.sync.aligned.m8n8.x4.shared.b16 {%0,%1,%2,%3}, [%4];"
                 : "=r"(r[0]), "=r"(r[1]), "=r"(r[2]), "=r"(r[3]) : "r"(addr));
}
__device__ __forceinline__ void mma_bf16(float* c, const uint32_t* a,
                                         uint32_t b0, uint32_t b1) {
    asm volatile(
        "mma.sync.aligned.m16n8k16.row.col.f32.bf16.bf16.f32 "
        "{%0,%1,%2,%3},{%4,%5,%6,%7},{%8,%9},{%0,%1,%2,%3};"
        : "+f"(c[0]), "+f"(c[1]), "+f"(c[2]), "+f"(c[3])
        : "r"(a[0]), "r"(a[1]), "r"(a[2]), "r"(a[3]), "r"(b0), "r"(b1));
}
#define SWZ(o) ((o) ^ (((o) >> 3) & 0x70))

__device__ __forceinline__ void split2(float a, float b, uint32_t& hi, uint32_t& lo) {
    __nv_bfloat16 ha = __float2bfloat16_rn(a);
    __nv_bfloat16 hb = __float2bfloat16_rn(b);
    __nv_bfloat16 la = __float2bfloat16_rn(a - __bfloat162float(ha));
    __nv_bfloat16 lb = __float2bfloat16_rn(b - __bfloat162float(hb));
    hi = (uint32_t)__bfloat16_as_ushort(ha) | ((uint32_t)__bfloat16_as_ushort(hb) << 16);
    lo = (uint32_t)__bfloat16_as_ushort(la) | ((uint32_t)__bfloat16_as_ushort(lb) << 16);
}

// MMA over one staged 128 x NT x 64 buffer (layout: AHI|ALO|BHI|BLO)
template <int NT>
__device__ __forceinline__ void mma_buf(uint32_t base, int lane, int wm, int wn,
                                        float (&acc)[4][NT / 32][4]) {
    constexpr int WN = NT / 4, NLD = WN / 16, NF = NT / 32;
    const int lrow = lane & 15, lkh = lane >> 4;
#pragma unroll
    for (int kk = 0; kk < 4; kk++) {
        const int kc = kk * 2 + lkh;
        uint32_t ahi[4][4], alo[4][4];
#pragma unroll
        for (int fm = 0; fm < 4; fm++) {
            uint32_t off = SWZ((uint32_t)((wm * 64 + fm * 16 + lrow) * 128 + kc * 16));
            ldsm_x4(base + off, ahi[fm]);
            ldsm_x4(base + 16384 + off, alo[fm]);
        }
        uint32_t bhi[NLD][4], blo[NLD][4];
#pragma unroll
        for (int fp = 0; fp < NLD; fp++) {
            uint32_t off = SWZ((uint32_t)((wn * WN + fp * 16 + lrow) * 128 + kc * 16));
            ldsm_x4(base + 32768 + off, bhi[fp]);
            ldsm_x4(base + 32768 + NT * 128 + off, blo[fp]);
        }
#pragma unroll
        for (int fm = 0; fm < 4; fm++)
#pragma unroll
            for (int fn = 0; fn < NF; fn++) {
                const int fp = fn >> 1, sel = fn & 1;
                mma_bf16(acc[fm][fn], ahi[fm], bhi[fp][sel], bhi[fp][sel + 2]);
                mma_bf16(acc[fm][fn], ahi[fm], blo[fp][sel], blo[fp][sel + 2]);
                mma_bf16(acc[fm][fn], alo[fm], bhi[fp][sel], bhi[fp][sel + 2]);
            }
    }
}

// ---------------------------------------------------------------------------
// Pipelined GEMM: C = A @ Bt^T (+bias). CTA 128 x N_TILE, chunk K=64,
// double-buffered smem, register-staged loads.
// ---------------------------------------------------------------------------
template <int N_TILE, bool BIAS>
__global__ __launch_bounds__(256, 1) void gemm_mma(
    const float* __restrict__ A, int lda, long long sA1, long long sA2,
    const float* __restrict__ Bt, int ldb, long long sB1, long long sB2,
    float* __restrict__ C, int ldc, long long sC1, long long sC2,
    int K, int zdiv, const float* __restrict__ bias) {
    extern __shared__ __align__(1024) char smem[];
    constexpr int NB = N_TILE / 16;
    constexpr int BUF = 32768 + 2 * N_TILE * 128;
    constexpr int NF = N_TILE / 32;

    const uint32_t sb = smem_u32(smem);
    const int tid = threadIdx.x, lane = tid & 31, w = tid >> 5;
    const int wm = w & 1, wn = w >> 1;
    const int z = blockIdx.z;
    A  += (long long)(z / zdiv) * sA1 + (long long)(z % zdiv) * sA2;
    Bt += (long long)(z / zdiv) * sB1 + (long long)(z % zdiv) * sB2;
    C  += (long long)(z / zdiv) * sC1 + (long long)(z % zdiv) * sC2;
    const int rowBase = blockIdx.y * 128, colBase = blockIdx.x * N_TILE;
    const int rA = tid >> 4, qA = tid & 15;
    const int nch = K >> 6;

    float4 ra[8], rb[NB];
    auto loadA = [&](int c) {
#pragma unroll
        for (int i = 0; i < 8; i++)
            ra[i] = *(const float4*)(A + (long long)(rowBase + rA + i * 16) * lda +
                                     c * 64 + qA * 4);
    };
    auto loadB = [&](int c) {
#pragma unroll
        for (int i = 0; i < NB; i++)
            rb[i] = *(const float4*)(Bt + (long long)(colBase + rA + i * 16) * ldb +
                                     c * 64 + qA * 4);
    };
    auto store = [&](int buf) {
        char* base = smem + buf * BUF;
#pragma unroll
        for (int i = 0; i < 8; i++) {
            uint32_t h01, l01, h23, l23;
            split2(ra[i].x, ra[i].y, h01, l01);
            split2(ra[i].z, ra[i].w, h23, l23);
            uint32_t off = SWZ((uint32_t)((rA + i * 16) * 128 + qA * 8));
            *(uint2*)(base + off) = make_uint2(h01, h23);
            *(uint2*)(base + 16384 + off) = make_uint2(l01, l23);
        }
#pragma unroll
        for (int i = 0; i < NB; i++) {
            uint32_t h01, l01, h23, l23;
            split2(rb[i].x, rb[i].y, h01, l01);
            split2(rb[i].z, rb[i].w, h23, l23);
            uint32_t off = SWZ((uint32_t)((rA + i * 16) * 128 + qA * 8));
            *(uint2*)(base + 32768 + off) = make_uint2(h01, h23);
            *(uint2*)(base + 32768 + N_TILE * 128 + off) = make_uint2(l01, l23);
        }
    };

    float acc[4][NF][4] = {};
    loadA(0); loadB(0); store(0);
    __syncthreads();
    for (int c = 0; c < nch; c++) {
        const int b = c & 1;
        if (c + 1 < nch) { loadA(c + 1); loadB(c + 1); }
        mma_buf<N_TILE>(sb + b * BUF, lane, wm, wn, acc);
        if (c + 1 < nch) store(1 - b);
        __syncthreads();
    }

    const long long erow = rowBase + wm * 64 + (lane >> 2);
    const int ecol = colBase + wn * (N_TILE / 4) + (lane & 3) * 2;
#pragma unroll
    for (int fm = 0; fm < 4; fm++)
#pragma unroll
        for (int fn = 0; fn < NF; fn++) {
            int cc = ecol + fn * 8;
            float b0 = BIAS ? bias[cc] : 0.f;
            float b1 = BIAS ? bias[cc + 1] : 0.f;
            long long r0 = erow + fm * 16;
            *(float2*)(C + r0 * ldc + cc) =
                make_float2(acc[fm][fn][0] + b0, acc[fm][fn][1] + b1);
            *(float2*)(C + (r0 + 8) * ldc + cc) =
                make_float2(acc[fm][fn][2] + b0, acc[fm][fn][3] + b1);
        }
}

// ---------------------------------------------------------------------------
// Scores: E = exp(QK^T/8), unnormalized, + per-tile row sums. grid(16,16,64)
// ---------------------------------------------------------------------------
__global__ __launch_bounds__(256, 1) void gemm_scores(
    const float* __restrict__ q, const float* __restrict__ k,
    float* __restrict__ attnw, float* __restrict__ partials) {
    extern __shared__ __align__(1024) char smem[];
    const uint32_t sb = smem_u32(smem);
    const int tid = threadIdx.x, lane = tid & 31, w = tid >> 5;
    const int wm = w & 1, wn = w >> 1;
    const int cx = blockIdx.x, cy = blockIdx.y, z = blockIdx.z;
    const int b = z >> 4, h = z & 15;
    const float* Aq = q + (long long)b * 2048 * 1024 + h * 64;
    const float* Ak = k + (long long)b * 2048 * 1024 + h * 64;
    const int rA = tid >> 4, qA = tid & 15;

#pragma unroll
    for (int i = 0; i < 8; i++) {
        int r = rA + i * 16;
        uint32_t h01, l01, h23, l23;
        uint32_t off = SWZ((uint32_t)(r * 128 + qA * 8));
        float4 x = *(const float4*)(Aq + (long long)(cy * 128 + r) * 1024 + qA * 4);
        split2(x.x, x.y, h01, l01);
        split2(x.z, x.w, h23, l23);
        *(uint2*)(smem + off) = make_uint2(h01, h23);
        *(uint2*)(smem + 16384 + off) = make_uint2(l01, l23);
        float4 y = *(const float4*)(Ak + (long long)(cx * 128 + r) * 1024 + qA * 4);
        split2(y.x, y.y, h01, l01);
        split2(y.z, y.w, h23, l23);
        *(uint2*)(smem + 32768 + off) = make_uint2(h01, h23);
        *(uint2*)(smem + 49152 + off) = make_uint2(l01, l23);
    }
    __syncthreads();

    float acc[4][4][4] = {};
    mma_buf<128>(sb, lane, wm, wn, acc);

    float* sums = (float*)(smem + 65536);  // [4][128]
    float* ab = attnw + (long long)z * cfg::SS;
    const int erow = wm * 64 + (lane >> 2);
    const int ecol = wn * 32 + (lane & 3) * 2;
#pragma unroll
    for (int fm = 0; fm < 4; fm++) {
        float s0 = 0.f, s1 = 0.f;
        int r0 = erow + fm * 16;
#pragma unroll
        for (int fn = 0; fn < 4; fn++) {
            int cc = ecol + fn * 8;
            float e0 = __expf(acc[fm][fn][0] * 0.125f);
            float e1 = __expf(acc[fm][fn][1] * 0.125f);
            float e2 = __expf(acc[fm][fn][2] * 0.125f);
            float e3 = __expf(acc[fm][fn][3] * 0.125f);
            *(float2*)(ab + (long long)(cy * 128 + r0) * 2048 + cx * 128 + cc) =
                make_float2(e0, e1);
            *(float2*)(ab + (long long)(cy * 128 + r0 + 8) * 2048 + cx * 128 + cc) =
                make_float2(e2, e3);
            s0 += e0 + e1;
            s1 += e2 + e3;
        }
        s0 += __shfl_xor_sync(~0u, s0, 1); s0 += __shfl_xor_sync(~0u, s0, 2);
        s1 += __shfl_xor_sync(~0u, s1, 1); s1 += __shfl_xor_sync(~0u, s1, 2);
        if ((lane & 3) == 0) {
            sums[wn * 128 + r0] = s0;
            sums[wn * 128 + r0 + 8] = s1;
        }
    }
    __syncthreads();
    if (tid < 128) {
        float t = sums[tid] + sums[128 + tid] + sums[256 + tid] + sums[384 + tid];
        partials[((long long)z * 16 + cx) * 2048 + cy * 128 + tid] = t;
    }
}

__global__ void reduce_inv(const float* __restrict__ p, float* __restrict__ inv) {
    int g = blockIdx.x * 256 + threadIdx.x;  // 0..131071
    int z = g >> 11, row = g & 2047;
    const float* base = p + (long long)z * 16 * 2048 + row;
    float s = 0.f;
#pragma unroll
    for (int i = 0; i < 16; i++) s += base[i * 2048];
    inv[g] = 1.f / s;
}

// ---------------------------------------------------------------------------
// PV: attn = softmax(E) @ V_h ; also writes normalized attn_weights in-place.
// grid(1, 16, 64), N tile 64, K=2048 (32 chunks), pipelined.
// ---------------------------------------------------------------------------
__global__ __launch_bounds__(256, 1) void gemm_pv(
    float* __restrict__ attnw, const float* __restrict__ vt,
    const float* __restrict__ inv, float* __restrict__ attn) {
    extern __shared__ __align__(1024) char smem[];
    constexpr int BUF = 49152;
    const uint32_t sb = smem_u32(smem);
    const int tid = threadIdx.x, lane = tid & 31, w = tid >> 5;
    const int wm = w & 1, wn = w >> 1;
    const int z = blockIdx.z, b = z >> 4, h = z & 15;
    const int rowBase = blockIdx.y * 128;
    float* Ab = attnw + (long long)z * cfg::SS;
    const float* Bb = vt + (long long)z * 64 * 2048;
    const int rA = tid >> 4, qA = tid & 15;

    float rinv[8];
#pragma unroll
    for (int i = 0; i < 8; i++) rinv[i] = inv[z * 2048 + rowBase + rA + i * 16];

    float4 ra[8], rb[4];
    int cs = 0;  // chunk staged in registers
    auto loadAB = [&](int c) {
        cs = c;
#pragma unroll
        for (int i = 0; i < 8; i++)
            ra[i] = *(const float4*)(Ab + (long long)(rowBase + rA + i * 16) * 2048 +
                                     c * 64 + qA * 4);
#pragma unroll
        for (int i = 0; i < 4; i++)
            rb[i] = *(const float4*)(Bb + (long long)(rA + i * 16) * 2048 +
                                     c * 64 + qA * 4);
    };
    auto store = [&](int buf) {
        char* base = smem + buf * BUF;
#pragma unroll
        for (int i = 0; i < 8; i++) {
            float4 x = ra[i];
            x.x *= rinv[i]; x.y *= rinv[i]; x.z *= rinv[i]; x.w *= rinv[i];
            *(float4*)(Ab + (long long)(rowBase + rA + i * 16) * 2048 +
                       cs * 64 + qA * 4) = x;  // normalized writeback
            uint32_t h01, l01, h23, l23;
            split2(x.x, x.y, h01, l01);
            split2(x.z, x.w, h23, l23);
            uint32_t off = SWZ((uint32_t)((rA + i * 16) * 128 + qA * 8));
            *(uint2*)(base + off) = make_uint2(h01, h23);
            *(uint2*)(base + 16384 + off) = make_uint2(l01, l23);
        }
#pragma unroll
        for (int i = 0; i < 4; i++) {
            uint32_t h01, l01, h23, l23;
            split2(rb[i].x, rb[i].y, h01, l01);
            split2(rb[i].z, rb[i].w, h23, l23);
            uint32_t off = SWZ((uint32_t)((rA + i * 16) * 128 + qA * 8));
            *(uint2*)(base + 32768 + off) = make_uint2(h01, h23);
            *(uint2*)(base + 32768 + 8192 + off) = make_uint2(l01, l23);
        }
    };

    float acc[4][2][4] = {};
    loadAB(0); store(0);
    __syncthreads();
    for (int c = 0; c < 32; c++) {
        const int bb = c & 1;
        if (c + 1 < 32) loadAB(c + 1);
        mma_buf<64>(sb + bb * BUF, lane, wm, wn, acc);
        if (c + 1 < 32) store(1 - bb);
        __syncthreads();
    }

    float* Cb = attn + (long long)b * 2048 * 1024 + h * 64;
    const long long erow = rowBase + wm * 64 + (lane >> 2);
    const int ecol = wn * 16 + (lane & 3) * 2;
#pragma unroll
    for (int fm = 0; fm < 4; fm++)
#pragma unroll
        for (int fn = 0; fn < 2; fn++) {
            int cc = ecol + fn * 8;
            long long r0 = erow + fm * 16;
            *(float2*)(Cb + r0 * 1024 + cc) =
                make_float2(acc[fm][fn][0], acc[fm][fn][1]);
            *(float2*)(Cb + (r0 + 8) * 1024 + cc) =
                make_float2(acc[fm][fn][2], acc[fm][fn][3]);
        }
}

// ---------------------------------------------------------------------------
__global__ void transpose_g(const float* __restrict__ in, int ldi,
                            long long si1, long long si2,
                            float* __restrict__ out, int ldo, long long so,
                            int zdiv) {
    __shared__ float tile[32][33];
    const int z = blockIdx.z;
    in  += (long long)(z / zdiv) * si1 + (long long)(z % zdiv) * si2;
    out += (long long)z * so;
    const int bx = blockIdx.x * 32, by = blockIdx.y * 32;
    const int tx = threadIdx.x, ty = threadIdx.y;  // 32 x 8
#pragma unroll
    for (int i = 0; i < 32; i += 8)
        tile[ty + i][tx] = in[(long long)(by + ty + i) * ldi + bx + tx];
    __syncthreads();
#pragma unroll
    for (int i = 0; i < 32; i += 8)
        out[(long long)(bx + ty + i) * ldo + by + tx] = tile[tx][ty + i];
}

__global__ void bo2_k(const float* __restrict__ bo, const float* __restrict__ Wo,
                      float* __restrict__ bo2) {
    int j = blockIdx.x * 256 + threadIdx.x;
    float s = bo[j];
#pragma unroll 8
    for (int k = 0; k < 1024; k++) s += bo[k] * Wo[k * 1024 + j];
    bo2[j] = s;
}

extern "C" void kernel_launch(void* const* d_in, const int* in_sizes, int n_in,
                              void* d_out, int out_size) {
    using namespace cfg;
    const float* values  = (const float*)d_in[0];
    const float* keys    = (const float*)d_in[1];
    const float* queries = (const float*)d_in[2];
    const float* Wq = (const float*)d_in[3];
    const float* bq = (const float*)d_in[4];
    const float* Wk = (const float*)d_in[5];
    const float* bk = (const float*)d_in[6];
    const float* Wv = (const float*)d_in[7];
    const float* bv = (const float*)d_in[8];
    const float* Wo = (const float*)d_in[9];
    const float* bo = (const float*)d_in[10];

    float* out   = (float*)d_out;
    float* attnw = out + BSD;

    float *q, *k, *v, *vt, *attn, *wqt, *wkt, *wvt, *wot, *wot2, *bo2, *part, *inv;
    cudaGetSymbolAddress((void**)&q, g_q);
    cudaGetSymbolAddress((void**)&k, g_k);
    cudaGetSymbolAddress((void**)&v, g_v);
    cudaGetSymbolAddress((void**)&vt, g_vt);
    cudaGetSymbolAddress((void**)&attn, g_attn);
    cudaGetSymbolAddress((void**)&wqt, g_wqt);
    cudaGetSymbolAddress((void**)&wkt, g_wkt);
    cudaGetSymbolAddress((void**)&wvt, g_wvt);
    cudaGetSymbolAddress((void**)&wot, g_wot);
    cudaGetSymbolAddress((void**)&wot2, g_wot2);
    cudaGetSymbolAddress((void**)&bo2, g_bo2);
    cudaGetSymbolAddress((void**)&part, g_partials);
    cudaGetSymbolAddress((void**)&inv, g_inv);

    constexpr int SMEM_G128 = 2 * (32768 + 2 * 128 * 128);  // 131072
    constexpr int SMEM_PV   = 2 * 49152;                    // 98304
    constexpr int SMEM_SC   = 65536 + 2048;                 // 67584
    cudaFuncSetAttribute(gemm_mma<128, true>,
                         cudaFuncAttributeMaxDynamicSharedMemorySize, SMEM_G128);
    cudaFuncSetAttribute(gemm_mma<128, false>,
                         cudaFuncAttributeMaxDynamicSharedMemorySize, SMEM_G128);
    cudaFuncSetAttribute(gemm_scores,
                         cudaFuncAttributeMaxDynamicSharedMemorySize, SMEM_SC);
    cudaFuncSetAttribute(gemm_pv,
                         cudaFuncAttributeMaxDynamicSharedMemorySize, SMEM_PV);

    const long long SD = (long long)S * D;

    // Weight transposes
    {
        dim3 blk(32, 8), grid(D / 32, D / 32, 1);
        transpose_g<<<grid, blk>>>(Wq, D, 0, 0, wqt, D, 0, 1);
        transpose_g<<<grid, blk>>>(Wk, D, 0, 0, wkt, D, 0, 1);
        transpose_g<<<grid, blk>>>(Wv, D, 0, 0, wvt, D, 0, 1);
        transpose_g<<<grid, blk>>>(Wo, D, 0, 0, wot, D, 0, 1);
    }
    // wot2 = Wo^T @ Wo^T = (Wo@Wo)^T ;  bo2 = bo@Wo + bo
    {
        dim3 grid(D / 128, D / 128, 1);
        gemm_mma<128, false><<<grid, 256, SMEM_G128>>>(
            wot, D, 0, 0, Wo, D, 0, 0, wot2, D, 0, 0, D, 1, nullptr);
        bo2_k<<<D / 256, 256>>>(bo, Wo, bo2);
    }
    // QKV projections
    {
        dim3 grid(D / 128, (int)(BS / 128), 1);
        gemm_mma<128, true><<<grid, 256, SMEM_G128>>>(
            queries, D, 0, 0, wqt, D, 0, 0, q, D, 0, 0, D, 1, bq);
        gemm_mma<128, true><<<grid, 256, SMEM_G128>>>(
            keys, D, 0, 0, wkt, D, 0, 0, k, D, 0, 0, D, 1, bk);
        gemm_mma<128, true><<<grid, 256, SMEM_G128>>>(
            values, D, 0, 0, wvt, D, 0, 0, v, D, 0, 0, D, 1, bv);
    }
    // V^T per (b,h)
    {
        dim3 blk(32, 8), grid(DK / 32, S / 32, B * H);
        transpose_g<<<grid, blk>>>(v, D, SD, (long long)DK, vt, S,
                                   (long long)DK * S, H);
    }
    // Scores -> unnormalized exp + partial sums
    {
        dim3 grid(16, 16, 64);
        gemm_scores<<<grid, 256, SMEM_SC>>>(q, k, attnw, part);
    }
    reduce_inv<<<512, 256>>>(part, inv);
    // PV + normalized attn_weights writeback
    {
        dim3 grid(1, 16, 64);
        gemm_pv<<<grid, 256, SMEM_PV>>>(attnw, vt, inv, attn);
    }
    // Fused double out-projection
    {
        dim3 grid(D / 128, (int)(BS / 128), 1);
        gemm_mma<128, true><<<grid, 256, SMEM_G128>>>(
            attn, D, 0, 0, wot2, D, 0, 0, out, D, 0, 0, D, 1, bo2);
    }
}

// round 6
// speedup vs baseline: 5.8101x; 1.3439x over previous
#include <cuda_runtime.h>
#include <cuda_bf16.h>
#include <math.h>
#include <stdint.h>

namespace cfg {
constexpr int B = 4, S = 2048, D = 1024, H = 16, DK = 64;
constexpr long long BS  = (long long)B * S;      // 8192
constexpr long long BSD = (long long)B * S * D;
constexpr long long SS  = (long long)S * S;
}

// ---------------------------------------------------------------------------
// Split-plane format for a matrix [rows x K] (K multiple of 64):
//   uint4 plane[chunk][hl][row][u]  (chunk = 64 cols, hl: 0=hi/1=lo,
//   u = 16B unit of 8 bf16, stored at u ^ (row & 7))  -> ldmatrix-ready image.
// ---------------------------------------------------------------------------
__device__ float g_v[8192 * 1024];           // fp32 V projection
__device__ float g_wqt[1024 * 1024];
__device__ float g_wkt[1024 * 1024];
__device__ float g_wvt[1024 * 1024];
__device__ float g_wot[1024 * 1024];
__device__ float g_bo2[1024];
__device__ float g_partials[64LL * 16 * 2048];
__device__ float g_inv[64 * 2048];

__device__ uint4 g_xq16[16LL * 2 * 8192 * 8];   // split inputs
__device__ uint4 g_xk16[16LL * 2 * 8192 * 8];
__device__ uint4 g_xv16[16LL * 2 * 8192 * 8];
__device__ uint4 g_wq16[16LL * 2 * 1024 * 8];   // split W^T
__device__ uint4 g_wk16[16LL * 2 * 1024 * 8];
__device__ uint4 g_wv16[16LL * 2 * 1024 * 8];
__device__ uint4 g_wot2_16[16LL * 2 * 1024 * 8];
__device__ uint4 g_q16[16LL * 2 * 8192 * 8];    // split Q, K projections
__device__ uint4 g_k16[16LL * 2 * 8192 * 8];
__device__ uint4 g_vt16[64LL * 32 * 2 * 64 * 8];  // per-(b,h) V^T
__device__ uint4 g_attn16[16LL * 2 * 8192 * 8];   // split PV output

// ---------------------------------------------------------------------------
__device__ __forceinline__ uint32_t smem_u32(const void* p) {
    uint32_t a;
    asm("{ .reg .u64 t; cvta.to.shared.u64 t, %1; cvt.u32.u64 %0, t; }"
        : "=r"(a) : "l"(p));
    return a;
}
__device__ __forceinline__ void ldsm_x4(uint32_t addr, uint32_t r[4]) {
    asm volatile("ldmatrix.sync.aligned.m8n8.x4.shared.b16 {%0,%1,%2,%3}, [%4];"
                 : "=r"(r[0]), "=r"(r[1]), "=r"(r[2]), "=r"(r[3]) : "r"(addr));
}
__device__ __forceinline__ void mma_bf16(float* c, const uint32_t* a,
                                         uint32_t b0, uint32_t b1) {
    asm volatile(
        "mma.sync.aligned.m16n8k16.row.col.f32.bf16.bf16.f32 "
        "{%0,%1,%2,%3},{%4,%5,%6,%7},{%8,%9},{%0,%1,%2,%3};"
        : "+f"(c[0]), "+f"(c[1]), "+f"(c[2]), "+f"(c[3])
        : "r"(a[0]), "r"(a[1]), "r"(a[2]), "r"(a[3]), "r"(b0), "r"(b1));
}
__device__ __forceinline__ void cp16(uint32_t dst, const void* src) {
    asm volatile("cp.async.cg.shared.global [%0], [%1], 16;" :: "r"(dst), "l"(src));
}
__device__ __forceinline__ void cp_commit() {
    asm volatile("cp.async.commit_group;" ::: "memory");
}
template <int N>
__device__ __forceinline__ void cp_wait() {
    asm volatile("cp.async.wait_group %0;" :: "n"(N) : "memory");
}
#define SWZ(o) ((o) ^ (((o) >> 3) & 0x70))

__device__ __forceinline__ void split2(float a, float b, uint32_t& hi, uint32_t& lo) {
    __nv_bfloat16 ha = __float2bfloat16_rn(a);
    __nv_bfloat16 hb = __float2bfloat16_rn(b);
    __nv_bfloat16 la = __float2bfloat16_rn(a - __bfloat162float(ha));
    __nv_bfloat16 lb = __float2bfloat16_rn(b - __bfloat162float(hb));
    hi = (uint32_t)__bfloat16_as_ushort(ha) | ((uint32_t)__bfloat16_as_ushort(hb) << 16);
    lo = (uint32_t)__bfloat16_as_ushort(la) | ((uint32_t)__bfloat16_as_ushort(lb) << 16);
}
__device__ __forceinline__ void split8(const float* v, uint4& hi, uint4& lo) {
    split2(v[0], v[1], hi.x, lo.x);
    split2(v[2], v[3], hi.y, lo.y);
    split2(v[4], v[5], hi.z, lo.z);
    split2(v[6], v[7], hi.w, lo.w);
}

// MMA over one staged 128 x NT x 64 buffer (layout: AHI|ALO|BHI|BLO)
template <int NT>
__device__ __forceinline__ void mma_buf(uint32_t base, int lane, int wm, int wn,
                                        float (&acc)[4][NT / 32][4]) {
    constexpr int WN = NT / 4, NLD = WN / 16, NF = NT / 32;
    const int lrow = lane & 15, lkh = lane >> 4;
#pragma unroll
    for (int kk = 0; kk < 4; kk++) {
        const int kc = kk * 2 + lkh;
        uint32_t ahi[4][4], alo[4][4];
#pragma unroll
        for (int fm = 0; fm < 4; fm++) {
            uint32_t off = SWZ((uint32_t)((wm * 64 + fm * 16 + lrow) * 128 + kc * 16));
            ldsm_x4(base + off, ahi[fm]);
            ldsm_x4(base + 16384 + off, alo[fm]);
        }
        uint32_t bhi[NLD][4], blo[NLD][4];
#pragma unroll
        for (int fp = 0; fp < NLD; fp++) {
            uint32_t off = SWZ((uint32_t)((wn * WN + fp * 16 + lrow) * 128 + kc * 16));
            ldsm_x4(base + 32768 + off, bhi[fp]);
            ldsm_x4(base + 32768 + NT * 128 + off, blo[fp]);
        }
#pragma unroll
        for (int fm = 0; fm < 4; fm++)
#pragma unroll
            for (int fn = 0; fn < NF; fn++) {
                const int fp = fn >> 1, sel = fn & 1;
                mma_bf16(acc[fm][fn], ahi[fm], bhi[fp][sel], bhi[fp][sel + 2]);
                mma_bf16(acc[fm][fn], ahi[fm], blo[fp][sel], blo[fp][sel + 2]);
                mma_bf16(acc[fm][fn], alo[fm], bhi[fp][sel], bhi[fp][sel + 2]);
            }
    }
}

// ---------------------------------------------------------------------------
// Unified 128x128 GEMM. LOADSPLIT: operands are split planes (cp.async,
// 3-stage). Else fp32 + in-kernel split (2-stage). EPISPLIT: write split
// planes (bias folded); else fp32 + bias.
// ---------------------------------------------------------------------------
template <bool BIAS, bool LOADSPLIT, bool EPISPLIT>
__global__ __launch_bounds__(256, 1) void gemm128(
    const float* __restrict__ A, int lda,
    const float* __restrict__ Bt, int ldb,
    const uint4* __restrict__ A16, long long rowsA,
    const uint4* __restrict__ B16, long long rowsB,
    float* __restrict__ C, int ldc,
    uint4* __restrict__ C16, long long rowsC,
    int nch, const float* __restrict__ bias) {
    extern __shared__ __align__(1024) char smem[];
    constexpr int BUFSZ = 65536;
    const uint32_t sb = smem_u32(smem);
    const int tid = threadIdx.x, lane = tid & 31, w = tid >> 5;
    const int wm = w & 1, wn = w >> 1;
    const long long rowBase = (long long)blockIdx.y * 128;
    const int colBase = blockIdx.x * 128;
    float acc[4][4][4] = {};

    if constexpr (LOADSPLIT) {
        auto issue = [&](int c, int buf) {
            uint32_t base = sb + buf * BUFSZ;
#pragma unroll
            for (int i = 0; i < 8; i++) {
                int e = tid + i * 256, hl = e >> 10, r = (e >> 3) & 127, j = e & 7;
                cp16(base + hl * 16384 + r * 128 + j * 16,
                     A16 + (((long long)c * 2 + hl) * rowsA + rowBase + r) * 8 + j);
            }
#pragma unroll
            for (int i = 0; i < 8; i++) {
                int e = tid + i * 256, hl = e >> 10, r = (e >> 3) & 127, j = e & 7;
                cp16(base + 32768 + hl * 16384 + r * 128 + j * 16,
                     B16 + (((long long)c * 2 + hl) * rowsB + colBase + r) * 8 + j);
            }
            cp_commit();
        };
        issue(0, 0);
        issue(1, 1);
        for (int c = 0; c < nch; c++) {
            if (c + 1 < nch) cp_wait<1>(); else cp_wait<0>();
            __syncthreads();
            mma_buf<128>(sb + (c % 3) * BUFSZ, lane, wm, wn, acc);
            if (c + 2 < nch) issue(c + 2, (c + 2) % 3);
        }
    } else {
        const int rA = tid >> 4, qA = tid & 15;
        float4 ra[8], rb[8];
        auto loadAB = [&](int c) {
#pragma unroll
            for (int i = 0; i < 8; i++)
                ra[i] = *(const float4*)(A + (rowBase + rA + i * 16) * lda +
                                         c * 64 + qA * 4);
#pragma unroll
            for (int i = 0; i < 8; i++)
                rb[i] = *(const float4*)(Bt + (long long)(colBase + rA + i * 16) * ldb +
                                         c * 64 + qA * 4);
        };
        auto store = [&](int buf) {
            char* base = smem + buf * BUFSZ;
#pragma unroll
            for (int i = 0; i < 8; i++) {
                uint32_t h01, l01, h23, l23;
                split2(ra[i].x, ra[i].y, h01, l01);
                split2(ra[i].z, ra[i].w, h23, l23);
                uint32_t off = SWZ((uint32_t)((rA + i * 16) * 128 + qA * 8));
                *(uint2*)(base + off) = make_uint2(h01, h23);
                *(uint2*)(base + 16384 + off) = make_uint2(l01, l23);
            }
#pragma unroll
            for (int i = 0; i < 8; i++) {
                uint32_t h01, l01, h23, l23;
                split2(rb[i].x, rb[i].y, h01, l01);
                split2(rb[i].z, rb[i].w, h23, l23);
                uint32_t off = SWZ((uint32_t)((rA + i * 16) * 128 + qA * 8));
                *(uint2*)(base + 32768 + off) = make_uint2(h01, h23);
                *(uint2*)(base + 49152 + off) = make_uint2(l01, l23);
            }
        };
        loadAB(0); store(0);
        __syncthreads();
        for (int c = 0; c < nch; c++) {
            const int b = c & 1;
            if (c + 1 < nch) loadAB(c + 1);
            mma_buf<128>(sb + b * BUFSZ, lane, wm, wn, acc);
            if (c + 1 < nch) store(1 - b);
            __syncthreads();
        }
    }
    __syncthreads();

    if constexpr (!EPISPLIT) {
        const long long erow = rowBase + wm * 64 + (lane >> 2);
        const int ecol = colBase + wn * 32 + (lane & 3) * 2;
#pragma unroll
        for (int fm = 0; fm < 4; fm++)
#pragma unroll
            for (int fn = 0; fn < 4; fn++) {
                int cc = ecol + fn * 8;
                float b0 = BIAS ? bias[cc] : 0.f;
                float b1 = BIAS ? bias[cc + 1] : 0.f;
                long long r0 = erow + fm * 16;
                *(float2*)(C + r0 * ldc + cc) =
                    make_float2(acc[fm][fn][0] + b0, acc[fm][fn][1] + b1);
                *(float2*)(C + (r0 + 8) * ldc + cc) =
                    make_float2(acc[fm][fn][2] + b0, acc[fm][fn][3] + b1);
            }
    } else {
        float* stage = (float*)smem;  // 128 x 132
        const int rl0 = wm * 64 + (lane >> 2), cl0 = wn * 32 + (lane & 3) * 2;
#pragma unroll
        for (int fm = 0; fm < 4; fm++)
#pragma unroll
            for (int fn = 0; fn < 4; fn++) {
                int r = rl0 + fm * 16, c = cl0 + fn * 8;
                stage[r * 132 + c] = acc[fm][fn][0];
                stage[r * 132 + c + 1] = acc[fm][fn][1];
                stage[(r + 8) * 132 + c] = acc[fm][fn][2];
                stage[(r + 8) * 132 + c + 1] = acc[fm][fn][3];
            }
        __syncthreads();
#pragma unroll
        for (int i = 0; i < 8; i++) {
            int e = tid + i * 256, r = e >> 4, u16 = e & 15;
            int gc = colBase + u16 * 8;
            float v[8];
#pragma unroll
            for (int j = 0; j < 8; j++) {
                v[j] = stage[r * 132 + u16 * 8 + j];
                if (BIAS) v[j] += bias[gc + j];
            }
            uint4 hi, lo;
            split8(v, hi, lo);
            long long chunk = (colBase >> 6) + (u16 >> 3);
            int uu = (u16 & 7) ^ (r & 7);
            C16[((chunk * 2 + 0) * rowsC + rowBase + r) * 8 + uu] = hi;
            C16[((chunk * 2 + 1) * rowsC + rowBase + r) * 8 + uu] = lo;
        }
    }
}

// ---------------------------------------------------------------------------
// Scores: E = exp(QK^T/8) (unnormalized) + per-tile row sums. grid(16,16,64)
// ---------------------------------------------------------------------------
__global__ __launch_bounds__(256, 1) void gemm_scores(
    const uint4* __restrict__ q16, const uint4* __restrict__ k16,
    float* __restrict__ attnw, float* __restrict__ partials) {
    extern __shared__ __align__(1024) char smem[];
    const uint32_t sb = smem_u32(smem);
    const int tid = threadIdx.x, lane = tid & 31, w = tid >> 5;
    const int wm = w & 1, wn = w >> 1;
    const int cx = blockIdx.x, cy = blockIdx.y, z = blockIdx.z;
    const int b = z >> 4, h = z & 15;
    const long long qrow = (long long)b * 2048 + cy * 128;
    const long long krow = (long long)b * 2048 + cx * 128;

#pragma unroll
    for (int i = 0; i < 8; i++) {
        int e = tid + i * 256, hl = e >> 10, r = (e >> 3) & 127, j = e & 7;
        cp16(sb + hl * 16384 + r * 128 + j * 16,
             q16 + (((long long)h * 2 + hl) * 8192 + qrow + r) * 8 + j);
        cp16(sb + 32768 + hl * 16384 + r * 128 + j * 16,
             k16 + (((long long)h * 2 + hl) * 8192 + krow + r) * 8 + j);
    }
    cp_commit();
    cp_wait<0>();
    __syncthreads();

    float acc[4][4][4] = {};
    mma_buf<128>(sb, lane, wm, wn, acc);

    float* sums = (float*)(smem + 65536);  // [4][128]
    float* ab = attnw + (long long)z * cfg::SS;
    const int erow = wm * 64 + (lane >> 2);
    const int ecol = wn * 32 + (lane & 3) * 2;
#pragma unroll
    for (int fm = 0; fm < 4; fm++) {
        float s0 = 0.f, s1 = 0.f;
        int r0 = erow + fm * 16;
#pragma unroll
        for (int fn = 0; fn < 4; fn++) {
            int cc = ecol + fn * 8;
            float e0 = __expf(acc[fm][fn][0] * 0.125f);
            float e1 = __expf(acc[fm][fn][1] * 0.125f);
            float e2 = __expf(acc[fm][fn][2] * 0.125f);
            float e3 = __expf(acc[fm][fn][3] * 0.125f);
            *(float2*)(ab + (long long)(cy * 128 + r0) * 2048 + cx * 128 + cc) =
                make_float2(e0, e1);
            *(float2*)(ab + (long long)(cy * 128 + r0 + 8) * 2048 + cx * 128 + cc) =
                make_float2(e2, e3);
            s0 += e0 + e1;
            s1 += e2 + e3;
        }
        s0 += __shfl_xor_sync(~0u, s0, 1); s0 += __shfl_xor_sync(~0u, s0, 2);
        s1 += __shfl_xor_sync(~0u, s1, 1); s1 += __shfl_xor_sync(~0u, s1, 2);
        if ((lane & 3) == 0) {
            sums[wn * 128 + r0] = s0;
            sums[wn * 128 + r0 + 8] = s1;
        }
    }
    __syncthreads();
    if (tid < 128) {
        float t = sums[tid] + sums[128 + tid] + sums[256 + tid] + sums[384 + tid];
        partials[((long long)z * 16 + cx) * 2048 + cy * 128 + tid] = t;
    }
}

__global__ void reduce_inv(const float* __restrict__ p, float* __restrict__ inv) {
    int g = blockIdx.x * 256 + threadIdx.x;
    int z = g >> 11, row = g & 2047;
    const float* base = p + (long long)z * 16 * 2048 + row;
    float s = 0.f;
#pragma unroll
    for (int i = 0; i < 16; i++) s += base[i * 2048];
    inv[g] = 1.f / s;
}

// ---------------------------------------------------------------------------
// PV: attn16 = softmax(E) @ V_h (split epilogue) + normalized writeback of E.
// grid(1, 16, 64)
// ---------------------------------------------------------------------------
__global__ __launch_bounds__(256, 1) void gemm_pv(
    float* __restrict__ attnw, const uint4* __restrict__ vt16,
    const float* __restrict__ inv, uint4* __restrict__ attn16) {
    extern __shared__ __align__(1024) char smem[];
    constexpr int BUF = 49152;
    const uint32_t sb = smem_u32(smem);
    const int tid = threadIdx.x, lane = tid & 31, w = tid >> 5;
    const int wm = w & 1, wn = w >> 1;
    const int z = blockIdx.z, b = z >> 4, h = z & 15;
    const int rowBase = blockIdx.y * 128;
    float* Ab = attnw + (long long)z * cfg::SS;
    const int rA = tid >> 4, qA = tid & 15;

    float rinv[8];
#pragma unroll
    for (int i = 0; i < 8; i++) rinv[i] = inv[z * 2048 + rowBase + rA + i * 16];

    float4 ra[8];
    int cs = 0;
    auto loadA = [&](int c) {
        cs = c;
#pragma unroll
        for (int i = 0; i < 8; i++)
            ra[i] = *(const float4*)(Ab + (long long)(rowBase + rA + i * 16) * 2048 +
                                     c * 64 + qA * 4);
    };
    auto issueB = [&](int c, int buf) {
#pragma unroll
        for (int i = 0; i < 4; i++) {
            int e = tid + i * 256, hl = e >> 9, r = (e >> 3) & 63, j = e & 7;
            cp16(sb + buf * BUF + 32768 + hl * 8192 + r * 128 + j * 16,
                 vt16 + ((((long long)z * 32 + c) * 2 + hl) * 64 + r) * 8 + j);
        }
        cp_commit();
    };
    auto storeA = [&](int buf) {
        char* base = smem + buf * BUF;
#pragma unroll
        for (int i = 0; i < 8; i++) {
            float4 x = ra[i];
            x.x *= rinv[i]; x.y *= rinv[i]; x.z *= rinv[i]; x.w *= rinv[i];
            *(float4*)(Ab + (long long)(rowBase + rA + i * 16) * 2048 +
                       cs * 64 + qA * 4) = x;  // normalized writeback
            uint32_t h01, l01, h23, l23;
            split2(x.x, x.y, h01, l01);
            split2(x.z, x.w, h23, l23);
            uint32_t off = SWZ((uint32_t)((rA + i * 16) * 128 + qA * 8));
            *(uint2*)(base + off) = make_uint2(h01, h23);
            *(uint2*)(base + 16384 + off) = make_uint2(l01, l23);
        }
    };

    float acc[4][2][4] = {};
    loadA(0); issueB(0, 0); storeA(0);
    cp_wait<0>();
    __syncthreads();
    for (int c = 0; c < 32; c++) {
        const int bb = c & 1;
        if (c + 1 < 32) { loadA(c + 1); issueB(c + 1, 1 - bb); }
        mma_buf<64>(sb + bb * BUF, lane, wm, wn, acc);
        if (c + 1 < 32) { storeA(1 - bb); cp_wait<0>(); }
        __syncthreads();
    }

    // epilogue: stage 128x64 tile, write split planes into attn16 (chunk = h)
    float* stage = (float*)smem;  // 128 x 68
    const int rl0 = wm * 64 + (lane >> 2), cl0 = wn * 16 + (lane & 3) * 2;
#pragma unroll
    for (int fm = 0; fm < 4; fm++)
#pragma unroll
        for (int fn = 0; fn < 2; fn++) {
            int r = rl0 + fm * 16, c = cl0 + fn * 8;
            stage[r * 68 + c] = acc[fm][fn][0];
            stage[r * 68 + c + 1] = acc[fm][fn][1];
            stage[(r + 8) * 68 + c] = acc[fm][fn][2];
            stage[(r + 8) * 68 + c + 1] = acc[fm][fn][3];
        }
    __syncthreads();
#pragma unroll
    for (int i = 0; i < 4; i++) {
        int e = tid + i * 256, r = e >> 3, u = e & 7;
        float v[8];
#pragma unroll
        for (int j = 0; j < 8; j++) v[j] = stage[r * 68 + u * 8 + j];
        uint4 hi, lo;
        split8(v, hi, lo);
        int uu = u ^ (r & 7);
        long long grow = (long long)b * 2048 + rowBase + r;
        attn16[(((long long)h * 2 + 0) * 8192 + grow) * 8 + uu] = hi;
        attn16[(((long long)h * 2 + 1) * 8192 + grow) * 8 + uu] = lo;
    }
}

// ---------------------------------------------------------------------------
// fp32 [rows][K] -> split planes. grid(K/64, rows/128), 256 thr
// ---------------------------------------------------------------------------
__global__ void convert_split(const float* __restrict__ X, long long rows, int K,
                              uint4* __restrict__ O) {
    const int chunk = blockIdx.x;
    const long long rb = (long long)blockIdx.y * 128;
    const int tid = threadIdx.x;
#pragma unroll
    for (int i = 0; i < 4; i++) {
        int e = tid + i * 256, r = e >> 3, u = e & 7;
        const float* src = X + (rb + r) * K + chunk * 64 + u * 8;
        float v[8];
        *(float4*)(v) = *(const float4*)(src);
        *(float4*)(v + 4) = *(const float4*)(src + 4);
        uint4 hi, lo;
        split8(v, hi, lo);
        int us = u ^ (r & 7);
        O[(((long long)chunk * 2 + 0) * rows + rb + r) * 8 + us] = hi;
        O[(((long long)chunk * 2 + 1) * rows + rb + r) * 8 + us] = lo;
    }
}

// V fp32 [8192][1024] -> split V^T planes per z. grid(32, 64), 256 thr
__global__ void transpose_split(const float* __restrict__ v, uint4* __restrict__ vt) {
    __shared__ float t[64][68];
    const int sc = blockIdx.x, z = blockIdx.y;
    const int b = z >> 4, h = z & 15;
    const int tid = threadIdx.x;
#pragma unroll
    for (int i = 0; i < 16; i++) {
        int e = tid + i * 256, si = e >> 6, dk = e & 63;
        t[dk][si] = v[((long long)b * 2048 + sc * 64 + si) * 1024 + h * 64 + dk];
    }
    __syncthreads();
#pragma unroll
    for (int i = 0; i < 2; i++) {
        int e = tid + i * 256, r = e >> 3, u = e & 7;
        float vv[8];
#pragma unroll
        for (int j = 0; j < 8; j++) vv[j] = t[r][u * 8 + j];
        uint4 hi, lo;
        split8(vv, hi, lo);
        int us = u ^ (r & 7);
        long long cb = ((long long)z * 32 + sc) * 2;
        vt[((cb + 0) * 64 + r) * 8 + us] = hi;
        vt[((cb + 1) * 64 + r) * 8 + us] = lo;
    }
}

__global__ void transpose_g(const float* __restrict__ in, float* __restrict__ out) {
    __shared__ float tile[32][33];
    const int bx = blockIdx.x * 32, by = blockIdx.y * 32;
    const int tx = threadIdx.x, ty = threadIdx.y;  // 32 x 8
#pragma unroll
    for (int i = 0; i < 32; i += 8)
        tile[ty + i][tx] = in[(long long)(by + ty + i) * 1024 + bx + tx];
    __syncthreads();
#pragma unroll
    for (int i = 0; i < 32; i += 8)
        out[(long long)(bx + ty + i) * 1024 + by + tx] = tile[tx][ty + i];
}

__global__ void bo2_k(const float* __restrict__ bo, const float* __restrict__ Wo,
                      float* __restrict__ bo2) {
    int j = blockIdx.x * 256 + threadIdx.x;
    float s = bo[j];
#pragma unroll 8
    for (int k = 0; k < 1024; k++) s += bo[k] * Wo[k * 1024 + j];
    bo2[j] = s;
}

extern "C" void kernel_launch(void* const* d_in, const int* in_sizes, int n_in,
                              void* d_out, int out_size) {
    using namespace cfg;
    const float* values  = (const float*)d_in[0];
    const float* keys    = (const float*)d_in[1];
    const float* queries = (const float*)d_in[2];
    const float* Wq = (const float*)d_in[3];
    const float* bq = (const float*)d_in[4];
    const float* Wk = (const float*)d_in[5];
    const float* bk = (const float*)d_in[6];
    const float* Wv = (const float*)d_in[7];
    const float* bv = (const float*)d_in[8];
    const float* Wo = (const float*)d_in[9];
    const float* bo = (const float*)d_in[10];

    float* out   = (float*)d_out;
    float* attnw = out + BSD;

    float *v, *wqt, *wkt, *wvt, *wot, *bo2, *part, *inv;
    uint4 *xq16, *xk16, *xv16, *wq16, *wk16, *wv16, *wot2_16;
    uint4 *q16, *k16, *vt16, *attn16;
    cudaGetSymbolAddress((void**)&v, g_v);
    cudaGetSymbolAddress((void**)&wqt, g_wqt);
    cudaGetSymbolAddress((void**)&wkt, g_wkt);
    cudaGetSymbolAddress((void**)&wvt, g_wvt);
    cudaGetSymbolAddress((void**)&wot, g_wot);
    cudaGetSymbolAddress((void**)&bo2, g_bo2);
    cudaGetSymbolAddress((void**)&part, g_partials);
    cudaGetSymbolAddress((void**)&inv, g_inv);
    cudaGetSymbolAddress((void**)&xq16, g_xq16);
    cudaGetSymbolAddress((void**)&xk16, g_xk16);
    cudaGetSymbolAddress((void**)&xv16, g_xv16);
    cudaGetSymbolAddress((void**)&wq16, g_wq16);
    cudaGetSymbolAddress((void**)&wk16, g_wk16);
    cudaGetSymbolAddress((void**)&wv16, g_wv16);
    cudaGetSymbolAddress((void**)&wot2_16, g_wot2_16);
    cudaGetSymbolAddress((void**)&q16, g_q16);
    cudaGetSymbolAddress((void**)&k16, g_k16);
    cudaGetSymbolAddress((void**)&vt16, g_vt16);
    cudaGetSymbolAddress((void**)&attn16, g_attn16);

    constexpr int SMEM_SPLIT = 3 * 65536;   // 196608
    constexpr int SMEM_CONV  = 2 * 65536;   // 131072
    constexpr int SMEM_SC    = 65536 + 2048;
    constexpr int SMEM_PV    = 2 * 49152;
    cudaFuncSetAttribute(gemm128<true, true, true>,
                         cudaFuncAttributeMaxDynamicSharedMemorySize, SMEM_SPLIT);
    cudaFuncSetAttribute(gemm128<true, true, false>,
                         cudaFuncAttributeMaxDynamicSharedMemorySize, SMEM_SPLIT);
    cudaFuncSetAttribute(gemm128<false, false, true>,
                         cudaFuncAttributeMaxDynamicSharedMemorySize, SMEM_CONV);
    cudaFuncSetAttribute(gemm_scores,
                         cudaFuncAttributeMaxDynamicSharedMemorySize, SMEM_SC);
    cudaFuncSetAttribute(gemm_pv,
                         cudaFuncAttributeMaxDynamicSharedMemorySize, SMEM_PV);

    dim3 tblk(32, 8), tgrid(32, 32, 1);
    transpose_g<<<tgrid, tblk>>>(Wq, wqt);
    transpose_g<<<tgrid, tblk>>>(Wk, wkt);
    transpose_g<<<tgrid, tblk>>>(Wv, wvt);
    transpose_g<<<tgrid, tblk>>>(Wo, wot);

    // Pre-split inputs and weights
    convert_split<<<dim3(16, 64), 256>>>(queries, 8192, 1024, xq16);
    convert_split<<<dim3(16, 64), 256>>>(keys,    8192, 1024, xk16);
    convert_split<<<dim3(16, 64), 256>>>(values,  8192, 1024, xv16);
    convert_split<<<dim3(16, 8), 256>>>(wqt, 1024, 1024, wq16);
    convert_split<<<dim3(16, 8), 256>>>(wkt, 1024, 1024, wk16);
    convert_split<<<dim3(16, 8), 256>>>(wvt, 1024, 1024, wv16);

    // wot2 = (Wo@Wo)^T as split planes; bo2 = bo@Wo + bo
    gemm128<false, false, true><<<dim3(8, 8), 256, SMEM_CONV>>>(
        wot, 1024, Wo, 1024, nullptr, 0, nullptr, 0,
        nullptr, 0, wot2_16, 1024, 16, nullptr);
    bo2_k<<<4, 256>>>(bo, Wo, bo2);

    // QKV projections (pure cp.async mainloops)
    gemm128<true, true, true><<<dim3(8, 64), 256, SMEM_SPLIT>>>(
        nullptr, 0, nullptr, 0, xq16, 8192, wq16, 1024,
        nullptr, 0, q16, 8192, 16, bq);
    gemm128<true, true, true><<<dim3(8, 64), 256, SMEM_SPLIT>>>(
        nullptr, 0, nullptr, 0, xk16, 8192, wk16, 1024,
        nullptr, 0, k16, 8192, 16, bk);
    gemm128<true, true, false><<<dim3(8, 64), 256, SMEM_SPLIT>>>(
        nullptr, 0, nullptr, 0, xv16, 8192, wv16, 1024,
        v, 1024, nullptr, 0, 16, bv);

    // V^T split planes per (b,h)
    transpose_split<<<dim3(32, 64), 256>>>(v, vt16);

    // Scores -> unnormalized exp + partial sums
    gemm_scores<<<dim3(16, 16, 64), 256, SMEM_SC>>>(q16, k16, attnw, part);
    reduce_inv<<<512, 256>>>(part, inv);

    // PV + normalized attn_weights writeback + split attn output
    gemm_pv<<<dim3(1, 16, 64), 256, SMEM_PV>>>(attnw, vt16, inv, attn16);

    // Fused double out-projection
    gemm128<true, true, false><<<dim3(8, 64), 256, SMEM_SPLIT>>>(
        nullptr, 0, nullptr, 0, attn16, 8192, wot2_16, 1024,
        out, 1024, nullptr, 0, 16, bo2);
}